// round 14
// baseline (speedup 1.0000x reference)
#include <cuda_runtime.h>
#include <cuda_bf16.h>
#include <math.h>
#include <stdint.h>

// ---------------------------------------------------------------------------
// Problem constants
// ---------------------------------------------------------------------------
#define BSZ   16
#define LSEQ  50
#define NBLK  64
#define DM    256
#define DH    512
#define KD    768
#define NVOC  65536
#define NTOK  (BSZ*LSEQ*NBLK)   // 51200
#define NBL   (BSZ*LSEQ)        // 800
#define SLOTS (LSEQ*NBLK)       // 3200 per batch

typedef __nv_bfloat16 bf16;

__device__ __forceinline__ float neg_inf() { return __int_as_float(0xff800000); }

// ---------------------------------------------------------------------------
// Scratch (static device globals; no allocation)
// ---------------------------------------------------------------------------
__device__ __align__(128) bf16  g_Hh[(size_t)NVOC*DH];  // relu hidden, bf16-hi
__device__ __align__(128) bf16  g_Hl[(size_t)NVOC*DH];  // relu hidden, bf16-lo
__device__ __align__(128) bf16  g_VTh[(size_t)NVOC*DM]; // v_text hi (post-LN)
__device__ __align__(128) bf16  g_VTl[(size_t)NVOC*DM]; // v_text lo (post-LN)
__device__ __align__(128) float g_KV[(size_t)NVOC*DM];  // v_text @ wk
__device__ __align__(128) float g_S2[(size_t)NVOC*DM];  // v_text @ am_w1[D:]
__device__ __align__(128) float g_S [NTOK];
__device__ __align__(128) float g_T [NBL*DM];
__device__ __align__(128) float g_QW[NBL*DM];

// pre-split TRANSPOSED weight planes ([N][K], k-contiguous): w1 | w2 | wk | am
#define OFF_W1 0
#define OFF_W2 393216
#define OFF_WK 524288
#define OFF_AM 589824
#define TOTW   655360
__device__ __align__(128) bf16 g_Bh[TOTW];
__device__ __align__(128) bf16 g_Bl[TOTW];

__device__ int   g_present[NVOC];
__device__ int   g_cidx[NVOC];
__device__ int   g_ulist[NVOC];
__device__ int   g_bsum[64];
__device__ int   g_ucnt[1];
__device__ int   g_tokc[NTOK];
__device__ int   g_selslot[NTOK];
__device__ int   g_fslot[BSZ*64];
__device__ int   g_fid  [BSZ*64];
__device__ __align__(128) float g_vfin[BSZ*DM];
__device__ __align__(128) float g_mfin[BSZ*DM];

// ---------------------------------------------------------------------------
// helpers
// ---------------------------------------------------------------------------
__device__ __forceinline__ void split_bf(float x, bf16& h, bf16& l)
{
    h = __float2bfloat16_rn(x);
    l = __float2bfloat16_rn(x - __bfloat162float(h));
}
__device__ __forceinline__ uint32_t pack2(bf16 a, bf16 b)
{
    return (uint32_t)__bfloat16_as_ushort(a) | ((uint32_t)__bfloat16_as_ushort(b) << 16);
}
__device__ __forceinline__ void mma_bf16(float c[4], const uint32_t a[4],
                                         uint32_t b0, uint32_t b1)
{
    asm volatile(
        "mma.sync.aligned.m16n8k16.row.col.f32.bf16.bf16.f32 "
        "{%0,%1,%2,%3}, {%4,%5,%6,%7}, {%8,%9}, {%0,%1,%2,%3};"
        : "+f"(c[0]), "+f"(c[1]), "+f"(c[2]), "+f"(c[3])
        : "r"(a[0]), "r"(a[1]), "r"(a[2]), "r"(a[3]), "r"(b0), "r"(b1));
}
__device__ __forceinline__ void ldsm_x4(uint32_t r[4], uint32_t saddr)
{
    asm volatile("ldmatrix.sync.aligned.m8n8.x4.shared.b16 {%0,%1,%2,%3}, [%4];"
        : "=r"(r[0]), "=r"(r[1]), "=r"(r[2]), "=r"(r[3]) : "r"(saddr));
}
__device__ __forceinline__ uint32_t s2u(const void* p)
{
    return (uint32_t)__cvta_generic_to_shared(p);
}
__device__ __forceinline__ void cpasync16(uint32_t dst, const void* src)
{
    asm volatile("cp.async.ca.shared.global [%0], [%1], 16;" :: "r"(dst), "l"(src));
}
#define CP_COMMIT() asm volatile("cp.async.commit_group;")

// ---------------------------------------------------------------------------
// Launch 0: zero present/ulist + tiled transpose-split of all weights
// ---------------------------------------------------------------------------
__global__ void prep0_k(const float* __restrict__ w1, const float* __restrict__ w2,
                        const float* __restrict__ wk, const float* __restrict__ am1)
{
    int bid = blockIdx.x, tid = threadIdx.x;
    if (bid < 256) g_present[bid*256 + tid] = 0;
    else if (bid < 512) g_ulist[(bid-256)*256 + tid] = 0;

    const float* W; bf16 *oh, *ol; int K, N, kt, nt;
    int id = bid;
    if (id < 384)      { W = w1;  oh = g_Bh+OFF_W1; ol = g_Bl+OFF_W1; K = KD; N = DH; kt = id % 24; nt = id / 24; }
    else if (id < 512) { id -= 384; W = w2;  oh = g_Bh+OFF_W2; ol = g_Bl+OFF_W2; K = DH; N = DM; kt = id % 16; nt = id / 16; }
    else if (id < 576) { id -= 512; W = wk;  oh = g_Bh+OFF_WK; ol = g_Bl+OFF_WK; K = DM; N = DM; kt = id % 8;  nt = id / 8; }
    else               { id -= 576; W = am1; oh = g_Bh+OFF_AM; ol = g_Bl+OFF_AM; K = DM; N = DM; kt = id % 8;  nt = id / 8; }

    __shared__ float t[32][33];
    int tx = tid & 31, ty = tid >> 5;
#pragma unroll
    for (int i = 0; i < 4; i++) {
        int k = kt*32 + ty + i*8, n = nt*32 + tx;
        t[ty + i*8][tx] = W[(size_t)k*N + n];
    }
    __syncthreads();
#pragma unroll
    for (int i = 0; i < 4; i++) {
        int n = nt*32 + ty + i*8, k = kt*32 + tx;
        split_bf(t[tx][ty + i*8], oh[(size_t)n*K + k], ol[(size_t)n*K + k]);
    }
}
__global__ void mark_k(const int* __restrict__ ids)
{
    int t = blockIdx.x * blockDim.x + threadIdx.x;
    if (t < NTOK) g_present[ids[t]] = 1;
}
// parallel scan: 64 blocks x 1024 local scan; scan3 folds in block offsets
__global__ void scan1_k()
{
    __shared__ int s[1024];
    int t = threadIdx.x, g = blockIdx.x * 1024 + t;
    int p = g_present[g];
    s[t] = p; __syncthreads();
    for (int off = 1; off < 1024; off <<= 1) {
        int v = (t >= off) ? s[t - off] : 0;
        __syncthreads();
        s[t] += v;
        __syncthreads();
    }
    g_cidx[g] = s[t] - p;
    if (t == 1023) g_bsum[blockIdx.x] = s[t];
}
__global__ void scan3_k()
{
    __shared__ int off_s;
    int t = threadIdx.x, g = blockIdx.x * 1024 + t;
    if (t == 0) {
        int run = 0;
        for (int i = 0; i < (int)blockIdx.x; i++) run += g_bsum[i];
        off_s = run;
        if (blockIdx.x == 63) g_ucnt[0] = run + g_bsum[63];
    }
    __syncthreads();
    int c = g_cidx[g] + off_s;
    g_cidx[g] = c;
    if (g_present[g]) g_ulist[c] = g;
}
__global__ void tokc_k(const int* __restrict__ ids)
{
    int t = blockIdx.x * blockDim.x + threadIdx.x;
    if (t < NTOK) g_tokc[t] = g_cidx[ids[t]];
}

// ---------------------------------------------------------------------------
// BF16 3-product split GEMM (h*h + l*h + h*l), fp32 accumulate.
// Block 128x256, BK=32, 512 threads (16 warps, 4m x 4n, warp tile 32x64).
// 3-stage cp.async ring (wait_group 1 keeps the next prefetch in flight
// during compute); ldmatrix.x4 fragments; pass-major MMA order.
// Per-element accumulation order (hh, lh, hl per k16, k ascending) is fixed
// => deterministic per gathered row => duplicate-id ties bitwise exact.
// fuse_ln: full-row LayerNorm epilogue, emit bf16 hi/lo planes.
// ---------------------------------------------------------------------------
#define A_STRB 40
#define A_PL   (128*A_STRB)                 // 5120 bf16
#define B_PL   (256*A_STRB)                 // 10240 bf16
#define BUF_E  (2*A_PL + 2*B_PL)            // 30720 bf16
#define BUF_B  (BUF_E*2)                    // 61440 bytes
#define NSTAGE 3
#define GEMM_SMEM (NSTAGE*BUF_B)            // 184320 bytes

__global__ void __launch_bounds__(512, 1) gemm_bf(
    const float* __restrict__ Araw,
    const bf16* __restrict__ AhG, const bf16* __restrict__ AlG,
    const bf16* __restrict__ Bh0, const bf16* __restrict__ Bl0,
    float* __restrict__ C0, const float* __restrict__ bias0,
    const bf16* __restrict__ Bh1, const bf16* __restrict__ Bl1,
    float* __restrict__ C1, const float* __restrict__ bias1,
    int Kdim, int Ndim,
    const int* __restrict__ gather,
    int act,
    const int* __restrict__ ucntp,
    int dual,
    bf16* __restrict__ Ch, bf16* __restrict__ Cl,
    const float* __restrict__ lng, const float* __restrict__ lnb,
    int fuse_ln)
{
    extern __shared__ bf16 smbf[];
    const int bm = blockIdx.x * 128;
    if (bm >= ucntp[0]) return;

    const bf16 *BhG, *BlG;
    const float* bias_;
    float* Cp;
    int bn;
    if (dual && blockIdx.y) { BhG = Bh1; BlG = Bl1; Cp = C1; bias_ = bias1; bn = 0; }
    else { BhG = Bh0; BlG = Bl0; Cp = C0; bias_ = bias0; bn = dual ? 0 : blockIdx.y * 256; }

    const int tid = threadIdx.x;
    const int wid = tid >> 5, lane = tid & 31;
    const int wm = (wid >> 2) * 32, wn = (wid & 3) * 64;
    const int grp = lane >> 2, qd = lane & 3;

    const int fa_row = tid >> 2, fa_q = tid & 3;
    const int fb_row = tid >> 1, fb_h = tid & 1;

    int ar = bm + fa_row;
    if (gather) ar = gather[ar];
    const bool gatherA = (Araw != nullptr);
    const float* ApR = gatherA ? (Araw + (size_t)ar * Kdim + fa_q * 8) : nullptr;
    const bf16* AhR = gatherA ? nullptr : (AhG + (size_t)(bm + fa_row) * Kdim + fa_q * 8);
    const bf16* AlR = gatherA ? nullptr : (AlG + (size_t)(bm + fa_row) * Kdim + fa_q * 8);
    const bf16* BhR = BhG + (size_t)(bn + fb_row) * Kdim;
    const bf16* BlR = BlG + (size_t)(bn + fb_row) * Kdim;

    float acc[2][8][4];
#pragma unroll
    for (int mi = 0; mi < 2; mi++)
#pragma unroll
        for (int ni = 0; ni < 8; ni++)
#pragma unroll
            for (int j = 0; j < 4; j++) acc[mi][ni][j] = 0.f;

    const int ktiles = Kdim >> 5;

    const uint32_t smBase = s2u(smbf);
    const uint32_t aFrag = (uint32_t)((wm + (lane & 15)) * (A_STRB*2)) + ((lane >> 4) * 16);
    const uint32_t bFrag = (uint32_t)(2*A_PL*2) +
        (uint32_t)((wn + (lane & 7) + ((lane >> 4) & 1) * 8) * (A_STRB*2)) +
        (((lane >> 3) & 1) * 16);

    auto issueB = [&](int bufo, int kt) {
        uint32_t dh = smBase + bufo + 2*A_PL*2 + (fb_row*A_STRB + fb_h*16) * 2;
        uint32_t dl = dh + B_PL*2;
        const bf16* sh = BhR + kt*32 + fb_h*16;
        const bf16* sl = BlR + kt*32 + fb_h*16;
        cpasync16(dh,      sh);
        cpasync16(dh + 16, sh + 8);
        cpasync16(dl,      sl);
        cpasync16(dl + 16, sl + 8);
    };
    auto issueA = [&](int bufo, int kt) {
        uint32_t dh = smBase + bufo + (fa_row*A_STRB + fa_q*8) * 2;
        cpasync16(dh,            AhR + kt*32);
        cpasync16(dh + A_PL*2,   AlR + kt*32);
    };
    auto stageAgather = [&](int bufo, int kt) {
        float4 v0 = *(const float4*)(ApR + kt*32);
        float4 v1 = *(const float4*)(ApR + kt*32 + 4);
        bf16 h[8], l[8];
        split_bf(v0.x, h[0], l[0]); split_bf(v0.y, h[1], l[1]);
        split_bf(v0.z, h[2], l[2]); split_bf(v0.w, h[3], l[3]);
        split_bf(v1.x, h[4], l[4]); split_bf(v1.y, h[5], l[5]);
        split_bf(v1.z, h[6], l[6]); split_bf(v1.w, h[7], l[7]);
        uint32_t off = bufo + (fa_row*A_STRB + fa_q*8) * 2;
        uint4 ph = make_uint4(pack2(h[0],h[1]), pack2(h[2],h[3]),
                              pack2(h[4],h[5]), pack2(h[6],h[7]));
        uint4 pl = make_uint4(pack2(l[0],l[1]), pack2(l[2],l[3]),
                              pack2(l[4],l[5]), pack2(l[6],l[7]));
        *(uint4*)((char*)smbf + off)           = ph;
        *(uint4*)((char*)smbf + off + A_PL*2)  = pl;
    };
    auto stage = [&](int bufo, int kt) {
        issueB(bufo, kt);
        if (gatherA) stageAgather(bufo, kt); else issueA(bufo, kt);
        CP_COMMIT();
    };

    // prologue: stages 0 and 1
    stage(0, 0);
    if (ktiles > 1) stage(BUF_B, 1);

    for (int kt = 0; kt < ktiles; kt++) {
        const int curo = (kt % NSTAGE) * BUF_B;
        if (kt + 1 < ktiles) asm volatile("cp.async.wait_group 1;");
        else                 asm volatile("cp.async.wait_group 0;");
        __syncthreads();
        if (kt + 2 < ktiles) stage(((kt + 2) % NSTAGE) * BUF_B, kt + 2);

#pragma unroll
        for (int k16 = 0; k16 < 2; k16++) {
            uint32_t aH[2][4], aL[2][4];
#pragma unroll
            for (int mi = 0; mi < 2; mi++) {
                uint32_t addr = smBase + curo + aFrag + mi*16*(A_STRB*2) + k16*32;
                ldsm_x4(aH[mi], addr);
                ldsm_x4(aL[mi], addr + A_PL*2);
            }
#pragma unroll
            for (int nig = 0; nig < 4; nig++) {
                uint32_t bH[4], bL[4];
                uint32_t addr = smBase + curo + bFrag + nig*16*(A_STRB*2) + k16*32;
                ldsm_x4(bH, addr);
                ldsm_x4(bL, addr + B_PL*2);
#pragma unroll
                for (int s = 0; s < 2; s++)
#pragma unroll
                    for (int mi = 0; mi < 2; mi++)
                        mma_bf16(acc[mi][nig*2+s], aH[mi], bH[2*s], bH[2*s+1]);
#pragma unroll
                for (int s = 0; s < 2; s++)
#pragma unroll
                    for (int mi = 0; mi < 2; mi++)
                        mma_bf16(acc[mi][nig*2+s], aL[mi], bH[2*s], bH[2*s+1]);
#pragma unroll
                for (int s = 0; s < 2; s++)
#pragma unroll
                    for (int mi = 0; mi < 2; mi++)
                        mma_bf16(acc[mi][nig*2+s], aH[mi], bL[2*s], bL[2*s+1]);
            }
        }
        __syncthreads();
    }

    if (!fuse_ln) {
#pragma unroll
        for (int mi = 0; mi < 2; mi++) {
            const int r0 = bm + wm + mi*16 + grp;
#pragma unroll
            for (int ni = 0; ni < 8; ni++) {
                const int n = bn + wn + ni*8 + qd*2;
                float b0 = bias_ ? bias_[n]   : 0.f;
                float b1 = bias_ ? bias_[n+1] : 0.f;
                float v0 = acc[mi][ni][0] + b0, v1 = acc[mi][ni][1] + b1;
                float v2 = acc[mi][ni][2] + b0, v3 = acc[mi][ni][3] + b1;
                if (act == 1) {
                    v0 = fmaxf(v0, 0.f); v1 = fmaxf(v1, 0.f);
                    v2 = fmaxf(v2, 0.f); v3 = fmaxf(v3, 0.f);
                }
                if (Cp) {
                    *(float2*)&Cp[(size_t)r0 * Ndim + n]     = make_float2(v0, v1);
                    *(float2*)&Cp[(size_t)(r0+8) * Ndim + n] = make_float2(v2, v3);
                }
                if (Ch) {
                    bf16 h0,l0,h1,l1,h2,l2,h3,l3;
                    split_bf(v0,h0,l0); split_bf(v1,h1,l1);
                    split_bf(v2,h2,l2); split_bf(v3,h3,l3);
                    *(uint32_t*)&Ch[(size_t)r0 * Ndim + n]     = pack2(h0, h1);
                    *(uint32_t*)&Ch[(size_t)(r0+8) * Ndim + n] = pack2(h2, h3);
                    *(uint32_t*)&Cl[(size_t)r0 * Ndim + n]     = pack2(l0, l1);
                    *(uint32_t*)&Cl[(size_t)(r0+8) * Ndim + n] = pack2(l2, l3);
                }
            }
        }
    } else {
        float* red = (float*)smbf;          // [128][17] padded
        float* mus = red + 128*17;
        float* sis = mus + 128;
        const int slot = (wid & 3)*4 + qd;

#pragma unroll
        for (int mi = 0; mi < 2; mi++) {
            const int lr = wm + mi*16 + grp;
            float s0 = 0.f, s1 = 0.f;
#pragma unroll
            for (int ni = 0; ni < 8; ni++) {
                const int n = wn + ni*8 + qd*2;
                float b0 = bias_[n], b1 = bias_[n+1];
                acc[mi][ni][0] += b0; acc[mi][ni][1] += b1;
                acc[mi][ni][2] += b0; acc[mi][ni][3] += b1;
                s0 += acc[mi][ni][0] + acc[mi][ni][1];
                s1 += acc[mi][ni][2] + acc[mi][ni][3];
            }
            red[lr*17 + slot]     = s0;
            red[(lr+8)*17 + slot] = s1;
        }
        __syncthreads();
        if (tid < 128) {
            float m = 0.f;
#pragma unroll
            for (int s = 0; s < 16; s++) m += red[tid*17 + s];
            mus[tid] = m * (1.f/DM);
        }
        __syncthreads();
#pragma unroll
        for (int mi = 0; mi < 2; mi++) {
            const int lr = wm + mi*16 + grp;
            float mu0 = mus[lr], mu1 = mus[lr+8];
            float s0 = 0.f, s1 = 0.f;
#pragma unroll
            for (int ni = 0; ni < 8; ni++) {
                float c0 = acc[mi][ni][0]-mu0, c1 = acc[mi][ni][1]-mu0;
                float c2 = acc[mi][ni][2]-mu1, c3 = acc[mi][ni][3]-mu1;
                s0 += c0*c0 + c1*c1;
                s1 += c2*c2 + c3*c3;
            }
            red[lr*17 + slot]     = s0;
            red[(lr+8)*17 + slot] = s1;
        }
        __syncthreads();
        if (tid < 128) {
            float v = 0.f;
#pragma unroll
            for (int s = 0; s < 16; s++) v += red[tid*17 + s];
            sis[tid] = rsqrtf(v * (1.f/DM) + 1e-5f);
        }
        __syncthreads();
#pragma unroll
        for (int mi = 0; mi < 2; mi++) {
            const int lr = wm + mi*16 + grp;
            const int r0 = bm + lr;
            float mu0 = mus[lr], is0 = sis[lr];
            float mu1 = mus[lr+8], is1 = sis[lr+8];
#pragma unroll
            for (int ni = 0; ni < 8; ni++) {
                const int n = wn + ni*8 + qd*2;
                float g0 = lng[n], g1 = lng[n+1], e0 = lnb[n], e1 = lnb[n+1];
                float v0 = g0*(acc[mi][ni][0]-mu0)*is0 + e0;
                float v1 = g1*(acc[mi][ni][1]-mu0)*is0 + e1;
                float v2 = g0*(acc[mi][ni][2]-mu1)*is1 + e0;
                float v3 = g1*(acc[mi][ni][3]-mu1)*is1 + e1;
                bf16 h0,l0,h1,l1,h2,l2,h3,l3;
                split_bf(v0,h0,l0); split_bf(v1,h1,l1);
                split_bf(v2,h2,l2); split_bf(v3,h3,l3);
                *(uint32_t*)&Ch[(size_t)r0 * Ndim + n]     = pack2(h0, h1);
                *(uint32_t*)&Ch[(size_t)(r0+8) * Ndim + n] = pack2(h2, h3);
                *(uint32_t*)&Cl[(size_t)r0 * Ndim + n]     = pack2(l0, l1);
                *(uint32_t*)&Cl[(size_t)(r0+8) * Ndim + n] = pack2(l2, l3);
            }
        }
    }
}

// ---------------------------------------------------------------------------
// Per-(b,l) precompute
// ---------------------------------------------------------------------------
__global__ void prep_k(const float* __restrict__ v, const float* __restrict__ tv,
                       const float* __restrict__ am_w1, const float* __restrict__ am_b1,
                       const float* __restrict__ wq)
{
    __shared__ float tvs[DM];
    __shared__ float qs[DM];
    int bl = blockIdx.x, d = threadIdx.x;
    float t0 = tv[(size_t)bl*DM + d];
    tvs[d] = t0;
    qs[d]  = t0 + v[(size_t)bl*DM + d];
    __syncthreads();
    float t = am_b1[d], q = 0.f;
    for (int k = 0; k < DM; k++) {
        t = fmaf(tvs[k], am_w1[k*DM + d], t);
        q = fmaf(qs[k],  wq  [k*DM + d], q);
    }
    g_T [(size_t)bl*DM + d] = t;
    g_QW[(size_t)bl*DM + d] = q;
}

// ---------------------------------------------------------------------------
// Per-token score (float4 loads; fixed per-(cidx,bl) accumulation order)
// ---------------------------------------------------------------------------
__global__ void score2_k(const float* __restrict__ am_w2)
{
    int tok  = blockIdx.x * 8 + (threadIdx.x >> 5);
    int lane = threadIdx.x & 31;
    int c  = g_tokc[tok];
    int bl = tok >> 6;
    const float4* s24 = (const float4*)(g_S2 + (size_t)c * DM);
    const float4* tt4 = (const float4*)(g_T  + (size_t)bl * DM);
    const float4* w4  = (const float4*)am_w2;
    float4 a0 = s24[lane*2],   a1 = s24[lane*2+1];
    float4 t0 = tt4[lane*2],   t1 = tt4[lane*2+1];
    float4 w0 = w4[lane*2],    w1 = w4[lane*2+1];
    float s = 0.f;
    s = fmaf(tanhf(a0.x + t0.x), w0.x, s);
    s = fmaf(tanhf(a0.y + t0.y), w0.y, s);
    s = fmaf(tanhf(a0.z + t0.z), w0.z, s);
    s = fmaf(tanhf(a0.w + t0.w), w0.w, s);
    s = fmaf(tanhf(a1.x + t1.x), w1.x, s);
    s = fmaf(tanhf(a1.y + t1.y), w1.y, s);
    s = fmaf(tanhf(a1.z + t1.z), w1.z, s);
    s = fmaf(tanhf(a1.w + t1.w), w1.w, s);
    for (int o = 16; o > 0; o >>= 1) s += __shfl_down_sync(0xffffffffu, s, o);
    if (lane == 0) g_S[tok] = s;
}

// ---------------------------------------------------------------------------
// Per-visit stable sort (softmax->mask->top_k(64 of 64) equivalent)
// ---------------------------------------------------------------------------
__global__ void select_k(const int* __restrict__ masks)
{
    int bl = blockIdx.x, j = threadIdx.x;
    __shared__ float key[64];
    int tok = bl*64 + j;
    float k_ = masks[tok] ? g_S[tok] : neg_inf();
    key[j] = k_; __syncthreads();
    int rank = 0;
    for (int m = 0; m < 64; m++) {
        float o = key[m];
        rank += (o > k_) || (o == k_ && m < j);
    }
    g_selslot[bl*64 + rank] = (bl % LSEQ) * NBLK + j;
}

// ---------------------------------------------------------------------------
// Sequential memory recurrence (half-warp per candidate + float4 rank scan)
// ---------------------------------------------------------------------------
__global__ void recur_k(const int* __restrict__ ids, const int* __restrict__ masks,
                        const int* __restrict__ lens)
{
    int b = blockIdx.x, tid = threadIdx.x;
    __shared__ __align__(16) float qw[DM];
    __shared__ int cslot[64], cmask[64];
    __shared__ int nslot[64], nmask[64];
    __shared__ int dslot[128], dmask[128], dcid[128];
    __shared__ float ev[128];
    __shared__ __align__(16) float mk[128];

    if (tid < 64) {
        int slot = g_selslot[(b*LSEQ + 0)*64 + tid];
        cslot[tid] = slot;
        cmask[tid] = masks[b*SLOTS + slot];
    }
    int lb = lens[b];
    __syncthreads();

    const int hw = tid >> 4, hl = tid & 15;

    for (int t = 1; t < LSEQ; t++) {
        qw[tid] = g_QW[(size_t)(b*LSEQ + t)*DM + tid];
        if (tid < 128) {
            int slot = (tid < 64) ? cslot[tid] : g_selslot[(b*LSEQ + t)*64 + (tid - 64)];
            dslot[tid] = slot;
            dmask[tid] = (tid < 64) ? cmask[tid] : masks[b*SLOTS + slot];
            dcid [tid] = g_tokc[b*SLOTS + slot];
        }
        __syncthreads();

        const float4* q4 = (const float4*)qw;
        float4 qv0 = q4[hl], qv1 = q4[hl+16], qv2 = q4[hl+32], qv3 = q4[hl+48];
        const float4* kv = (const float4*)(g_KV + (size_t)dcid[hw] * DM);
        float4 k0 = kv[hl], k1 = kv[hl+16], k2 = kv[hl+32], k3 = kv[hl+48];
        for (int c = hw; c < 128; c += 16) {
            const bool hasnext = (c + 16 < 128);
            float4 n0, n1, n2, n3;
            if (hasnext) {
                const float4* kn = (const float4*)(g_KV + (size_t)dcid[c + 16] * DM);
                n0 = kn[hl]; n1 = kn[hl+16]; n2 = kn[hl+32]; n3 = kn[hl+48];
            }
            float s = k0.x*qv0.x + k0.y*qv0.y + k0.z*qv0.z + k0.w*qv0.w
                    + k1.x*qv1.x + k1.y*qv1.y + k1.z*qv1.z + k1.w*qv1.w
                    + k2.x*qv2.x + k2.y*qv2.y + k2.z*qv2.z + k2.w*qv2.w
                    + k3.x*qv3.x + k3.y*qv3.y + k3.z*qv3.z + k3.w*qv3.w;
            for (int o = 8; o > 0; o >>= 1) s += __shfl_down_sync(0xffffffffu, s, o, 16);
            if (hl == 0) ev[c] = s;
            if (hasnext) { k0 = n0; k1 = n1; k2 = n2; k3 = n3; }
        }
        __syncthreads();

        if (tid < 128) mk[tid] = dmask[tid] ? ev[tid] : neg_inf();
        __syncthreads();

        if (tid < 128) {
            float k_ = mk[tid];
            int rank = 0;
            const float4* m4 = (const float4*)mk;
#pragma unroll 8
            for (int i = 0; i < 32; i++) {
                float4 o4 = m4[i];
                int mb = i*4;
                rank += (o4.x > k_) || (o4.x == k_ && mb+0 < tid);
                rank += (o4.y > k_) || (o4.y == k_ && mb+1 < tid);
                rank += (o4.z > k_) || (o4.z == k_ && mb+2 < tid);
                rank += (o4.w > k_) || (o4.w == k_ && mb+3 < tid);
            }
            if (rank < 64) { nslot[rank] = dslot[tid]; nmask[rank] = dmask[tid]; }
        }
        __syncthreads();
        if (tid < 64) {
            cslot[tid] = nslot[tid];
            cmask[tid] = nmask[tid];
            if (t == lb - 1) g_fslot[b*64 + tid] = nslot[tid];
        }
        __syncthreads();
    }
}

// ---------------------------------------------------------------------------
// Pools (VT reconstructed as hi+lo; max-pool path, 1e-3 tolerance)
// ---------------------------------------------------------------------------
__global__ void final_k(const float* __restrict__ tv, const int* __restrict__ ids,
                        const int* __restrict__ lens)
{
    int b = blockIdx.x, d = threadIdx.x;
    int lb = lens[b];
    float mx = neg_inf();
    for (int l = 0; l < lb; l++) mx = fmaxf(mx, tv[((size_t)b*LSEQ + l)*DM + d]);
    g_vfin[b*DM + d] = mx;
    float mv = neg_inf();
    for (int m = 0; m < 64; m++) {
        int c = g_tokc[b*SLOTS + g_fslot[b*64 + m]];
        float vt = __bfloat162float(g_VTh[(size_t)c*DM + d])
                 + __bfloat162float(g_VTl[(size_t)c*DM + d]);
        mv = fmaxf(mv, vt);
    }
    g_mfin[b*DM + d] = mv;
    if (d < 64) g_fid[b*64 + d] = ids[b*SLOTS + g_fslot[b*64 + d]];
}

// ---------------------------------------------------------------------------
// Output head + flatten
// ---------------------------------------------------------------------------
__global__ void out_k(const float* __restrict__ ow, const float* __restrict__ ob,
                      float* __restrict__ out, int out_size)
{
    int tid = threadIdx.x;
    if (tid < 32) {
        int b = tid >> 1, o = tid & 1;
        float v = ob[o];
        for (int d = 0; d < DM; d++) v = fmaf(g_vfin[b*DM + d], ow[d*2 + o], v);
        for (int d = 0; d < DM; d++) v = fmaf(g_mfin[b*DM + d], ow[(DM + d)*2 + o], v);
        if (tid < out_size) out[tid] = v;
    }
    for (int i = tid; i < BSZ*64; i += blockDim.x)
        if (32 + i < out_size) out[32 + i] = (float)g_fid[i];
    for (int i = 32 + BSZ*64 + tid; i < out_size; i += blockDim.x)
        out[i] = 0.f;
}

// ---------------------------------------------------------------------------
// Launch
// ---------------------------------------------------------------------------
extern "C" void kernel_launch(void* const* d_in, const int* in_sizes, int n_in,
                              void* d_out, int out_size)
{
    const float* v_all  = (const float*)d_in[0];
    const float* tv_all = (const float*)d_in[1];
    const float* emb    = (const float*)d_in[2];
    const float* w1     = (const float*)d_in[3];
    const float* b1     = (const float*)d_in[4];
    const float* w2     = (const float*)d_in[5];
    const float* b2     = (const float*)d_in[6];
    const float* gam    = (const float*)d_in[7];
    const float* bet    = (const float*)d_in[8];
    const float* wq     = (const float*)d_in[9];
    const float* wk     = (const float*)d_in[10];
    const float* amw1   = (const float*)d_in[11];
    const float* amb1   = (const float*)d_in[12];
    const float* amw2   = (const float*)d_in[13];
    const float* ow     = (const float*)d_in[14];
    const float* ob     = (const float*)d_in[15];
    const int*   itxt   = (const int*)d_in[16];
    const int*   mtxt   = (const int*)d_in[17];
    const int*   lens   = (const int*)d_in[18];
    float* out = (float*)d_out;

    bf16 *pHh, *pHl, *pVTh, *pVTl, *pBh, *pBl;
    float *pKV, *pS2;
    int *pU, *pUL;
    cudaGetSymbolAddress((void**)&pHh,  g_Hh);
    cudaGetSymbolAddress((void**)&pHl,  g_Hl);
    cudaGetSymbolAddress((void**)&pVTh, g_VTh);
    cudaGetSymbolAddress((void**)&pVTl, g_VTl);
    cudaGetSymbolAddress((void**)&pKV,  g_KV);
    cudaGetSymbolAddress((void**)&pS2,  g_S2);
    cudaGetSymbolAddress((void**)&pBh,  g_Bh);
    cudaGetSymbolAddress((void**)&pBl,  g_Bl);
    cudaGetSymbolAddress((void**)&pU,   g_ucnt);
    cudaGetSymbolAddress((void**)&pUL,  g_ulist);

    cudaFuncSetAttribute(gemm_bf, cudaFuncAttributeMaxDynamicSharedMemorySize, GEMM_SMEM);

    // dedup + weight split (scan2 folded into scan3)
    prep0_k<<<640, 256>>>(w1, w2, wk, amw1 + DM*DM);
    mark_k<<<NTOK/256, 256>>>(itxt);
    scan1_k<<<64, 1024>>>();
    scan3_k<<<64, 1024>>>();

    // GEMM1: relu(emb[gather] @ w1 + b1) -> bf16 planes g_Hh/g_Hl
    gemm_bf<<<dim3(NVOC/128, 2), 512, GEMM_SMEM>>>(
        emb, nullptr, nullptr,
        pBh + OFF_W1, pBl + OFF_W1, nullptr, b1,
        nullptr, nullptr, nullptr, nullptr,
        KD, DH, pUL, 1, pU, 0, pHh, pHl, nullptr, nullptr, 0);

    tokc_k<<<NTOK/256, 256>>>(itxt);
    prep_k<<<NBL, DM>>>(v_all, tv_all, amw1, amb1, wq);

    // GEMM2 + fused LayerNorm: VT = LN(Hplanes @ w2 + b2) -> g_VTh/g_VTl
    gemm_bf<<<dim3(NVOC/128, 1), 512, GEMM_SMEM>>>(
        nullptr, pHh, pHl,
        pBh + OFF_W2, pBl + OFF_W2, nullptr, b2,
        nullptr, nullptr, nullptr, nullptr,
        DH, DM, nullptr, 0, pU, 0, pVTh, pVTl, gam, bet, 1);

    // GEMM3+4 fused: KV = VT @ wk ; S2 = VT @ am_w1[D:]
    gemm_bf<<<dim3(NVOC/128, 2), 512, GEMM_SMEM>>>(
        nullptr, pVTh, pVTl,
        pBh + OFF_WK, pBl + OFF_WK, pKV, nullptr,
        pBh + OFF_AM, pBl + OFF_AM, pS2, nullptr,
        DM, DM, nullptr, 0, pU, 1, nullptr, nullptr, nullptr, nullptr, 0);

    // score + selection + recurrence + pooling + head
    score2_k<<<NTOK/8, 256>>>(amw2);
    select_k<<<NBL, 64>>>(mtxt);
    recur_k<<<BSZ, 256>>>(itxt, mtxt, lens);
    final_k<<<BSZ, DM>>>(tv_all, itxt, lens);
    out_k<<<1, 256>>>(ow, ob, out, out_size);
}

// round 15
// speedup vs baseline: 1.0579x; 1.0579x over previous
#include <cuda_runtime.h>
#include <cuda_bf16.h>
#include <math.h>
#include <stdint.h>

// ---------------------------------------------------------------------------
// Problem constants
// ---------------------------------------------------------------------------
#define BSZ   16
#define LSEQ  50
#define NBLK  64
#define DM    256
#define DH    512
#define KD    768
#define NVOC  65536
#define NTOK  (BSZ*LSEQ*NBLK)   // 51200
#define NBL   (BSZ*LSEQ)        // 800
#define SLOTS (LSEQ*NBLK)       // 3200 per batch

typedef __nv_bfloat16 bf16;

__device__ __forceinline__ float neg_inf() { return __int_as_float(0xff800000); }

// ---------------------------------------------------------------------------
// Scratch (static device globals; no allocation)
// ---------------------------------------------------------------------------
__device__ __align__(128) bf16  g_Hh[(size_t)NVOC*DH];  // relu hidden, bf16-hi
__device__ __align__(128) bf16  g_Hl[(size_t)NVOC*DH];  // relu hidden, bf16-lo
__device__ __align__(128) bf16  g_VTh[(size_t)NVOC*DM]; // v_text hi (post-LN)
__device__ __align__(128) bf16  g_VTl[(size_t)NVOC*DM]; // v_text lo (post-LN)
__device__ __align__(128) float g_KV[(size_t)NVOC*DM];  // v_text @ wk
__device__ __align__(128) float g_S2[(size_t)NVOC*DM];  // v_text @ am_w1[D:]
__device__ __align__(128) float g_T [NBL*DM];
__device__ __align__(128) float g_QW[NBL*DM];

// pre-split TRANSPOSED weight planes ([N][K], k-contiguous): w1 | w2 | wk | am
#define OFF_W1 0
#define OFF_W2 393216
#define OFF_WK 524288
#define OFF_AM 589824
#define TOTW   655360
__device__ __align__(128) bf16 g_Bh[TOTW];
__device__ __align__(128) bf16 g_Bl[TOTW];

__device__ int   g_present[NVOC];
__device__ int   g_cidx[NVOC];
__device__ int   g_ulist[NVOC];
__device__ int   g_bsum[64];
__device__ int   g_ucnt[1];
__device__ int   g_tokc[NTOK];
__device__ int   g_selslot[NTOK];
__device__ int   g_fslot[BSZ*64];
__device__ int   g_fid  [BSZ*64];
__device__ __align__(128) float g_vfin[BSZ*DM];
__device__ __align__(128) float g_mfin[BSZ*DM];

// ---------------------------------------------------------------------------
// helpers
// ---------------------------------------------------------------------------
__device__ __forceinline__ void split_bf(float x, bf16& h, bf16& l)
{
    h = __float2bfloat16_rn(x);
    l = __float2bfloat16_rn(x - __bfloat162float(h));
}
__device__ __forceinline__ uint32_t pack2(bf16 a, bf16 b)
{
    return (uint32_t)__bfloat16_as_ushort(a) | ((uint32_t)__bfloat16_as_ushort(b) << 16);
}
__device__ __forceinline__ void mma_bf16(float c[4], const uint32_t a[4],
                                         uint32_t b0, uint32_t b1)
{
    asm volatile(
        "mma.sync.aligned.m16n8k16.row.col.f32.bf16.bf16.f32 "
        "{%0,%1,%2,%3}, {%4,%5,%6,%7}, {%8,%9}, {%0,%1,%2,%3};"
        : "+f"(c[0]), "+f"(c[1]), "+f"(c[2]), "+f"(c[3])
        : "r"(a[0]), "r"(a[1]), "r"(a[2]), "r"(a[3]), "r"(b0), "r"(b1));
}
__device__ __forceinline__ void ldsm_x4(uint32_t r[4], uint32_t saddr)
{
    asm volatile("ldmatrix.sync.aligned.m8n8.x4.shared.b16 {%0,%1,%2,%3}, [%4];"
        : "=r"(r[0]), "=r"(r[1]), "=r"(r[2]), "=r"(r[3]) : "r"(saddr));
}
__device__ __forceinline__ uint32_t s2u(const void* p)
{
    return (uint32_t)__cvta_generic_to_shared(p);
}
__device__ __forceinline__ void cpasync16(uint32_t dst, const void* src)
{
    asm volatile("cp.async.ca.shared.global [%0], [%1], 16;" :: "r"(dst), "l"(src));
}
#define CP_COMMIT() asm volatile("cp.async.commit_group;")
#define CP_WAIT0()  asm volatile("cp.async.wait_group 0;")

// ---------------------------------------------------------------------------
// Launch 0: zero present/ulist + tiled transpose-split of all weights
// ---------------------------------------------------------------------------
__global__ void prep0_k(const float* __restrict__ w1, const float* __restrict__ w2,
                        const float* __restrict__ wk, const float* __restrict__ am1)
{
    int bid = blockIdx.x, tid = threadIdx.x;
    if (bid < 256) g_present[bid*256 + tid] = 0;
    else if (bid < 512) g_ulist[(bid-256)*256 + tid] = 0;

    const float* W; bf16 *oh, *ol; int K, N, kt, nt;
    int id = bid;
    if (id < 384)      { W = w1;  oh = g_Bh+OFF_W1; ol = g_Bl+OFF_W1; K = KD; N = DH; kt = id % 24; nt = id / 24; }
    else if (id < 512) { id -= 384; W = w2;  oh = g_Bh+OFF_W2; ol = g_Bl+OFF_W2; K = DH; N = DM; kt = id % 16; nt = id / 16; }
    else if (id < 576) { id -= 512; W = wk;  oh = g_Bh+OFF_WK; ol = g_Bl+OFF_WK; K = DM; N = DM; kt = id % 8;  nt = id / 8; }
    else               { id -= 576; W = am1; oh = g_Bh+OFF_AM; ol = g_Bl+OFF_AM; K = DM; N = DM; kt = id % 8;  nt = id / 8; }

    __shared__ float t[32][33];
    int tx = tid & 31, ty = tid >> 5;
#pragma unroll
    for (int i = 0; i < 4; i++) {
        int k = kt*32 + ty + i*8, n = nt*32 + tx;
        t[ty + i*8][tx] = W[(size_t)k*N + n];
    }
    __syncthreads();
#pragma unroll
    for (int i = 0; i < 4; i++) {
        int n = nt*32 + ty + i*8, k = kt*32 + tx;
        split_bf(t[tx][ty + i*8], oh[(size_t)n*K + k], ol[(size_t)n*K + k]);
    }
}
__global__ void mark_k(const int* __restrict__ ids)
{
    int t = blockIdx.x * blockDim.x + threadIdx.x;
    if (t < NTOK) g_present[ids[t]] = 1;
}
// parallel scan: 64 blocks x 1024 local scan; scan3 folds in block offsets
__global__ void scan1_k()
{
    __shared__ int s[1024];
    int t = threadIdx.x, g = blockIdx.x * 1024 + t;
    int p = g_present[g];
    s[t] = p; __syncthreads();
    for (int off = 1; off < 1024; off <<= 1) {
        int v = (t >= off) ? s[t - off] : 0;
        __syncthreads();
        s[t] += v;
        __syncthreads();
    }
    g_cidx[g] = s[t] - p;
    if (t == 1023) g_bsum[blockIdx.x] = s[t];
}
__global__ void scan3_k()
{
    __shared__ int off_s;
    int t = threadIdx.x, g = blockIdx.x * 1024 + t;
    if (t == 0) {
        int run = 0;
        for (int i = 0; i < (int)blockIdx.x; i++) run += g_bsum[i];
        off_s = run;
        if (blockIdx.x == 63) g_ucnt[0] = run + g_bsum[63];
    }
    __syncthreads();
    int c = g_cidx[g] + off_s;
    g_cidx[g] = c;
    if (g_present[g]) g_ulist[c] = g;
}
__global__ void tokc_k(const int* __restrict__ ids)
{
    int t = blockIdx.x * blockDim.x + threadIdx.x;
    if (t < NTOK) g_tokc[t] = g_cidx[ids[t]];
}

// ---------------------------------------------------------------------------
// BF16 3-product split GEMM (h*h + l*h + h*l), fp32 accumulate.
// Block 128x256, BK=32, 512 threads (16 warps, 4m x 4n, warp tile 32x64).
// PROVEN 2-stage double buffer (122,880 B smem keeps ~105 KB L1 for reused
// B-plane caching; depth-3 measured -47 us regression). ldmatrix.x4;
// pass-major MMA order; fixed hh,lh,hl per-k16 accumulation => deterministic
// per gathered row => duplicate-id ties bitwise exact.
// fuse_ln: full-row LayerNorm epilogue, emit bf16 hi/lo planes.
// ---------------------------------------------------------------------------
#define A_STRB 40
#define A_PL   (128*A_STRB)                 // 5120 bf16
#define B_PL   (256*A_STRB)                 // 10240 bf16
#define BUF_E  (2*A_PL + 2*B_PL)            // 30720 bf16
#define BUF_B  (BUF_E*2)                    // 61440 bytes
#define GEMM_SMEM (2*BUF_B)                 // 122880 bytes

__global__ void __launch_bounds__(512, 1) gemm_bf(
    const float* __restrict__ Araw,
    const bf16* __restrict__ AhG, const bf16* __restrict__ AlG,
    const bf16* __restrict__ Bh0, const bf16* __restrict__ Bl0,
    float* __restrict__ C0, const float* __restrict__ bias0,
    const bf16* __restrict__ Bh1, const bf16* __restrict__ Bl1,
    float* __restrict__ C1, const float* __restrict__ bias1,
    int Kdim, int Ndim,
    const int* __restrict__ gather,
    int act,
    const int* __restrict__ ucntp,
    int dual,
    bf16* __restrict__ Ch, bf16* __restrict__ Cl,
    const float* __restrict__ lng, const float* __restrict__ lnb,
    int fuse_ln)
{
    extern __shared__ bf16 smbf[];
    const int bm = blockIdx.x * 128;
    if (bm >= ucntp[0]) return;

    const bf16 *BhG, *BlG;
    const float* bias_;
    float* Cp;
    int bn;
    if (dual && blockIdx.y) { BhG = Bh1; BlG = Bl1; Cp = C1; bias_ = bias1; bn = 0; }
    else { BhG = Bh0; BlG = Bl0; Cp = C0; bias_ = bias0; bn = dual ? 0 : blockIdx.y * 256; }

    const int tid = threadIdx.x;
    const int wid = tid >> 5, lane = tid & 31;
    const int wm = (wid >> 2) * 32, wn = (wid & 3) * 64;
    const int grp = lane >> 2, qd = lane & 3;

    const int fa_row = tid >> 2, fa_q = tid & 3;
    const int fb_row = tid >> 1, fb_h = tid & 1;

    int ar = bm + fa_row;
    if (gather) ar = gather[ar];
    const bool gatherA = (Araw != nullptr);
    const float* ApR = gatherA ? (Araw + (size_t)ar * Kdim + fa_q * 8) : nullptr;
    const bf16* AhR = gatherA ? nullptr : (AhG + (size_t)(bm + fa_row) * Kdim + fa_q * 8);
    const bf16* AlR = gatherA ? nullptr : (AlG + (size_t)(bm + fa_row) * Kdim + fa_q * 8);
    const bf16* BhR = BhG + (size_t)(bn + fb_row) * Kdim;
    const bf16* BlR = BlG + (size_t)(bn + fb_row) * Kdim;

    float acc[2][8][4];
#pragma unroll
    for (int mi = 0; mi < 2; mi++)
#pragma unroll
        for (int ni = 0; ni < 8; ni++)
#pragma unroll
            for (int j = 0; j < 4; j++) acc[mi][ni][j] = 0.f;

    const int ktiles = Kdim >> 5;

    const uint32_t smBase = s2u(smbf);
    const uint32_t aFrag = (uint32_t)((wm + (lane & 15)) * (A_STRB*2)) + ((lane >> 4) * 16);
    const uint32_t bFrag = (uint32_t)(2*A_PL*2) +
        (uint32_t)((wn + (lane & 7) + ((lane >> 4) & 1) * 8) * (A_STRB*2)) +
        (((lane >> 3) & 1) * 16);

    auto issueB = [&](int bufo, int kt) {
        uint32_t dh = smBase + bufo + 2*A_PL*2 + (fb_row*A_STRB + fb_h*16) * 2;
        uint32_t dl = dh + B_PL*2;
        const bf16* sh = BhR + kt*32 + fb_h*16;
        const bf16* sl = BlR + kt*32 + fb_h*16;
        cpasync16(dh,      sh);
        cpasync16(dh + 16, sh + 8);
        cpasync16(dl,      sl);
        cpasync16(dl + 16, sl + 8);
    };
    auto issueA = [&](int bufo, int kt) {
        uint32_t dh = smBase + bufo + (fa_row*A_STRB + fa_q*8) * 2;
        cpasync16(dh,            AhR + kt*32);
        cpasync16(dh + A_PL*2,   AlR + kt*32);
    };
    auto stageAgather = [&](int bufo, int kt) {
        float4 v0 = *(const float4*)(ApR + kt*32);
        float4 v1 = *(const float4*)(ApR + kt*32 + 4);
        bf16 h[8], l[8];
        split_bf(v0.x, h[0], l[0]); split_bf(v0.y, h[1], l[1]);
        split_bf(v0.z, h[2], l[2]); split_bf(v0.w, h[3], l[3]);
        split_bf(v1.x, h[4], l[4]); split_bf(v1.y, h[5], l[5]);
        split_bf(v1.z, h[6], l[6]); split_bf(v1.w, h[7], l[7]);
        uint32_t off = bufo + (fa_row*A_STRB + fa_q*8) * 2;
        uint4 ph = make_uint4(pack2(h[0],h[1]), pack2(h[2],h[3]),
                              pack2(h[4],h[5]), pack2(h[6],h[7]));
        uint4 pl = make_uint4(pack2(l[0],l[1]), pack2(l[2],l[3]),
                              pack2(l[4],l[5]), pack2(l[6],l[7]));
        *(uint4*)((char*)smbf + off)           = ph;
        *(uint4*)((char*)smbf + off + A_PL*2)  = pl;
    };

    // prologue: stage 0 -> buffer 0
    issueB(0, 0);
    if (gatherA) stageAgather(0, 0); else issueA(0, 0);
    CP_COMMIT(); CP_WAIT0();
    __syncthreads();

    for (int kt = 0; kt < ktiles; kt++) {
        const int curo = (kt & 1) * BUF_B;
        const int nxto = curo ^ BUF_B;
        const bool more = (kt + 1 < ktiles);
        if (more) {
            issueB(nxto, kt + 1);
            if (gatherA) stageAgather(nxto, kt + 1); else issueA(nxto, kt + 1);
            CP_COMMIT();
        }

#pragma unroll
        for (int k16 = 0; k16 < 2; k16++) {
            uint32_t aH[2][4], aL[2][4];
#pragma unroll
            for (int mi = 0; mi < 2; mi++) {
                uint32_t addr = smBase + curo + aFrag + mi*16*(A_STRB*2) + k16*32;
                ldsm_x4(aH[mi], addr);
                ldsm_x4(aL[mi], addr + A_PL*2);
            }
#pragma unroll
            for (int nig = 0; nig < 4; nig++) {
                uint32_t bH[4], bL[4];
                uint32_t addr = smBase + curo + bFrag + nig*16*(A_STRB*2) + k16*32;
                ldsm_x4(bH, addr);
                ldsm_x4(bL, addr + B_PL*2);
#pragma unroll
                for (int s = 0; s < 2; s++)
#pragma unroll
                    for (int mi = 0; mi < 2; mi++)
                        mma_bf16(acc[mi][nig*2+s], aH[mi], bH[2*s], bH[2*s+1]);
#pragma unroll
                for (int s = 0; s < 2; s++)
#pragma unroll
                    for (int mi = 0; mi < 2; mi++)
                        mma_bf16(acc[mi][nig*2+s], aL[mi], bH[2*s], bH[2*s+1]);
#pragma unroll
                for (int s = 0; s < 2; s++)
#pragma unroll
                    for (int mi = 0; mi < 2; mi++)
                        mma_bf16(acc[mi][nig*2+s], aH[mi], bL[2*s], bL[2*s+1]);
            }
        }

        if (more) CP_WAIT0();
        __syncthreads();
    }

    if (!fuse_ln) {
#pragma unroll
        for (int mi = 0; mi < 2; mi++) {
            const int r0 = bm + wm + mi*16 + grp;
#pragma unroll
            for (int ni = 0; ni < 8; ni++) {
                const int n = bn + wn + ni*8 + qd*2;
                float b0 = bias_ ? bias_[n]   : 0.f;
                float b1 = bias_ ? bias_[n+1] : 0.f;
                float v0 = acc[mi][ni][0] + b0, v1 = acc[mi][ni][1] + b1;
                float v2 = acc[mi][ni][2] + b0, v3 = acc[mi][ni][3] + b1;
                if (act == 1) {
                    v0 = fmaxf(v0, 0.f); v1 = fmaxf(v1, 0.f);
                    v2 = fmaxf(v2, 0.f); v3 = fmaxf(v3, 0.f);
                }
                if (Cp) {
                    *(float2*)&Cp[(size_t)r0 * Ndim + n]     = make_float2(v0, v1);
                    *(float2*)&Cp[(size_t)(r0+8) * Ndim + n] = make_float2(v2, v3);
                }
                if (Ch) {
                    bf16 h0,l0,h1,l1,h2,l2,h3,l3;
                    split_bf(v0,h0,l0); split_bf(v1,h1,l1);
                    split_bf(v2,h2,l2); split_bf(v3,h3,l3);
                    *(uint32_t*)&Ch[(size_t)r0 * Ndim + n]     = pack2(h0, h1);
                    *(uint32_t*)&Ch[(size_t)(r0+8) * Ndim + n] = pack2(h2, h3);
                    *(uint32_t*)&Cl[(size_t)r0 * Ndim + n]     = pack2(l0, l1);
                    *(uint32_t*)&Cl[(size_t)(r0+8) * Ndim + n] = pack2(l2, l3);
                }
            }
        }
    } else {
        float* red = (float*)smbf;          // [128][17] padded
        float* mus = red + 128*17;
        float* sis = mus + 128;
        const int slot = (wid & 3)*4 + qd;

#pragma unroll
        for (int mi = 0; mi < 2; mi++) {
            const int lr = wm + mi*16 + grp;
            float s0 = 0.f, s1 = 0.f;
#pragma unroll
            for (int ni = 0; ni < 8; ni++) {
                const int n = wn + ni*8 + qd*2;
                float b0 = bias_[n], b1 = bias_[n+1];
                acc[mi][ni][0] += b0; acc[mi][ni][1] += b1;
                acc[mi][ni][2] += b0; acc[mi][ni][3] += b1;
                s0 += acc[mi][ni][0] + acc[mi][ni][1];
                s1 += acc[mi][ni][2] + acc[mi][ni][3];
            }
            red[lr*17 + slot]     = s0;
            red[(lr+8)*17 + slot] = s1;
        }
        __syncthreads();
        if (tid < 128) {
            float m = 0.f;
#pragma unroll
            for (int s = 0; s < 16; s++) m += red[tid*17 + s];
            mus[tid] = m * (1.f/DM);
        }
        __syncthreads();
#pragma unroll
        for (int mi = 0; mi < 2; mi++) {
            const int lr = wm + mi*16 + grp;
            float mu0 = mus[lr], mu1 = mus[lr+8];
            float s0 = 0.f, s1 = 0.f;
#pragma unroll
            for (int ni = 0; ni < 8; ni++) {
                float c0 = acc[mi][ni][0]-mu0, c1 = acc[mi][ni][1]-mu0;
                float c2 = acc[mi][ni][2]-mu1, c3 = acc[mi][ni][3]-mu1;
                s0 += c0*c0 + c1*c1;
                s1 += c2*c2 + c3*c3;
            }
            red[lr*17 + slot]     = s0;
            red[(lr+8)*17 + slot] = s1;
        }
        __syncthreads();
        if (tid < 128) {
            float v = 0.f;
#pragma unroll
            for (int s = 0; s < 16; s++) v += red[tid*17 + s];
            sis[tid] = rsqrtf(v * (1.f/DM) + 1e-5f);
        }
        __syncthreads();
#pragma unroll
        for (int mi = 0; mi < 2; mi++) {
            const int lr = wm + mi*16 + grp;
            const int r0 = bm + lr;
            float mu0 = mus[lr], is0 = sis[lr];
            float mu1 = mus[lr+8], is1 = sis[lr+8];
#pragma unroll
            for (int ni = 0; ni < 8; ni++) {
                const int n = wn + ni*8 + qd*2;
                float g0 = lng[n], g1 = lng[n+1], e0 = lnb[n], e1 = lnb[n+1];
                float v0 = g0*(acc[mi][ni][0]-mu0)*is0 + e0;
                float v1 = g1*(acc[mi][ni][1]-mu0)*is0 + e1;
                float v2 = g0*(acc[mi][ni][2]-mu1)*is1 + e0;
                float v3 = g1*(acc[mi][ni][3]-mu1)*is1 + e1;
                bf16 h0,l0,h1,l1,h2,l2,h3,l3;
                split_bf(v0,h0,l0); split_bf(v1,h1,l1);
                split_bf(v2,h2,l2); split_bf(v3,h3,l3);
                *(uint32_t*)&Ch[(size_t)r0 * Ndim + n]     = pack2(h0, h1);
                *(uint32_t*)&Ch[(size_t)(r0+8) * Ndim + n] = pack2(h2, h3);
                *(uint32_t*)&Cl[(size_t)r0 * Ndim + n]     = pack2(l0, l1);
                *(uint32_t*)&Cl[(size_t)(r0+8) * Ndim + n] = pack2(l2, l3);
            }
        }
    }
}

// ---------------------------------------------------------------------------
// Per-(b,l) precompute
// ---------------------------------------------------------------------------
__global__ void prep_k(const float* __restrict__ v, const float* __restrict__ tv,
                       const float* __restrict__ am_w1, const float* __restrict__ am_b1,
                       const float* __restrict__ wq)
{
    __shared__ float tvs[DM];
    __shared__ float qs[DM];
    int bl = blockIdx.x, d = threadIdx.x;
    float t0 = tv[(size_t)bl*DM + d];
    tvs[d] = t0;
    qs[d]  = t0 + v[(size_t)bl*DM + d];
    __syncthreads();
    float t = am_b1[d], q = 0.f;
    for (int k = 0; k < DM; k++) {
        t = fmaf(tvs[k], am_w1[k*DM + d], t);
        q = fmaf(qs[k],  wq  [k*DM + d], q);
    }
    g_T [(size_t)bl*DM + d] = t;
    g_QW[(size_t)bl*DM + d] = q;
}

// ---------------------------------------------------------------------------
// Fused per-visit score + stable sort. One block per (b,l) visit.
// Each warp computes 8 token scores with the SAME lane-strided float4
// accumulation order as before (bitwise-identical per (cidx,bl)); then the
// 64-wide masked stable rank selects, replicating softmax->mask->top_k.
// ---------------------------------------------------------------------------
__global__ void scorsel_k(const float* __restrict__ am_w2,
                          const int* __restrict__ masks)
{
    int bl = blockIdx.x;
    int tid = threadIdx.x, wid = tid >> 5, lane = tid & 31;
    __shared__ float key[64];

    const float4* tt4 = (const float4*)(g_T + (size_t)bl * DM);
    const float4* w4  = (const float4*)am_w2;
    float4 t0 = tt4[lane*2], t1 = tt4[lane*2+1];
    float4 w0 = w4[lane*2],  w1 = w4[lane*2+1];

#pragma unroll
    for (int i = 0; i < 8; i++) {
        int j = wid*8 + i;
        int tok = bl*64 + j;
        int c = g_tokc[tok];
        const float4* s24 = (const float4*)(g_S2 + (size_t)c * DM);
        float4 a0 = s24[lane*2], a1 = s24[lane*2+1];
        float s = 0.f;
        s = fmaf(tanhf(a0.x + t0.x), w0.x, s);
        s = fmaf(tanhf(a0.y + t0.y), w0.y, s);
        s = fmaf(tanhf(a0.z + t0.z), w0.z, s);
        s = fmaf(tanhf(a0.w + t0.w), w0.w, s);
        s = fmaf(tanhf(a1.x + t1.x), w1.x, s);
        s = fmaf(tanhf(a1.y + t1.y), w1.y, s);
        s = fmaf(tanhf(a1.z + t1.z), w1.z, s);
        s = fmaf(tanhf(a1.w + t1.w), w1.w, s);
        for (int o = 16; o > 0; o >>= 1) s += __shfl_down_sync(0xffffffffu, s, o);
        if (lane == 0) key[j] = masks[tok] ? s : neg_inf();
    }
    __syncthreads();

    if (tid < 64) {
        int j = tid;
        float k_ = key[j];
        int rank = 0;
        for (int m = 0; m < 64; m++) {
            float o = key[m];
            rank += (o > k_) || (o == k_ && m < j);
        }
        g_selslot[bl*64 + rank] = (bl % LSEQ) * NBLK + j;
    }
}

// ---------------------------------------------------------------------------
// Sequential memory recurrence (half-warp per candidate + float4 rank scan)
// ---------------------------------------------------------------------------
__global__ void recur_k(const int* __restrict__ ids, const int* __restrict__ masks,
                        const int* __restrict__ lens)
{
    int b = blockIdx.x, tid = threadIdx.x;
    __shared__ __align__(16) float qw[DM];
    __shared__ int cslot[64], cmask[64];
    __shared__ int nslot[64], nmask[64];
    __shared__ int dslot[128], dmask[128], dcid[128];
    __shared__ float ev[128];
    __shared__ __align__(16) float mk[128];

    if (tid < 64) {
        int slot = g_selslot[(b*LSEQ + 0)*64 + tid];
        cslot[tid] = slot;
        cmask[tid] = masks[b*SLOTS + slot];
    }
    int lb = lens[b];
    __syncthreads();

    const int hw = tid >> 4, hl = tid & 15;

    for (int t = 1; t < LSEQ; t++) {
        qw[tid] = g_QW[(size_t)(b*LSEQ + t)*DM + tid];
        if (tid < 128) {
            int slot = (tid < 64) ? cslot[tid] : g_selslot[(b*LSEQ + t)*64 + (tid - 64)];
            dslot[tid] = slot;
            dmask[tid] = (tid < 64) ? cmask[tid] : masks[b*SLOTS + slot];
            dcid [tid] = g_tokc[b*SLOTS + slot];
        }
        __syncthreads();

        const float4* q4 = (const float4*)qw;
        float4 qv0 = q4[hl], qv1 = q4[hl+16], qv2 = q4[hl+32], qv3 = q4[hl+48];
        const float4* kv = (const float4*)(g_KV + (size_t)dcid[hw] * DM);
        float4 k0 = kv[hl], k1 = kv[hl+16], k2 = kv[hl+32], k3 = kv[hl+48];
        for (int c = hw; c < 128; c += 16) {
            const bool hasnext = (c + 16 < 128);
            float4 n0, n1, n2, n3;
            if (hasnext) {
                const float4* kn = (const float4*)(g_KV + (size_t)dcid[c + 16] * DM);
                n0 = kn[hl]; n1 = kn[hl+16]; n2 = kn[hl+32]; n3 = kn[hl+48];
            }
            float s = k0.x*qv0.x + k0.y*qv0.y + k0.z*qv0.z + k0.w*qv0.w
                    + k1.x*qv1.x + k1.y*qv1.y + k1.z*qv1.z + k1.w*qv1.w
                    + k2.x*qv2.x + k2.y*qv2.y + k2.z*qv2.z + k2.w*qv2.w
                    + k3.x*qv3.x + k3.y*qv3.y + k3.z*qv3.z + k3.w*qv3.w;
            for (int o = 8; o > 0; o >>= 1) s += __shfl_down_sync(0xffffffffu, s, o, 16);
            if (hl == 0) ev[c] = s;
            if (hasnext) { k0 = n0; k1 = n1; k2 = n2; k3 = n3; }
        }
        __syncthreads();

        if (tid < 128) mk[tid] = dmask[tid] ? ev[tid] : neg_inf();
        __syncthreads();

        if (tid < 128) {
            float k_ = mk[tid];
            int rank = 0;
            const float4* m4 = (const float4*)mk;
#pragma unroll 8
            for (int i = 0; i < 32; i++) {
                float4 o4 = m4[i];
                int mb = i*4;
                rank += (o4.x > k_) || (o4.x == k_ && mb+0 < tid);
                rank += (o4.y > k_) || (o4.y == k_ && mb+1 < tid);
                rank += (o4.z > k_) || (o4.z == k_ && mb+2 < tid);
                rank += (o4.w > k_) || (o4.w == k_ && mb+3 < tid);
            }
            if (rank < 64) { nslot[rank] = dslot[tid]; nmask[rank] = dmask[tid]; }
        }
        __syncthreads();
        if (tid < 64) {
            cslot[tid] = nslot[tid];
            cmask[tid] = nmask[tid];
            if (t == lb - 1) g_fslot[b*64 + tid] = nslot[tid];
        }
        __syncthreads();
    }
}

// ---------------------------------------------------------------------------
// Pools (VT reconstructed as hi+lo; max-pool path, 1e-3 tolerance)
// ---------------------------------------------------------------------------
__global__ void final_k(const float* __restrict__ tv, const int* __restrict__ ids,
                        const int* __restrict__ lens)
{
    int b = blockIdx.x, d = threadIdx.x;
    int lb = lens[b];
    float mx = neg_inf();
    for (int l = 0; l < lb; l++) mx = fmaxf(mx, tv[((size_t)b*LSEQ + l)*DM + d]);
    g_vfin[b*DM + d] = mx;
    float mv = neg_inf();
    for (int m = 0; m < 64; m++) {
        int c = g_tokc[b*SLOTS + g_fslot[b*64 + m]];
        float vt = __bfloat162float(g_VTh[(size_t)c*DM + d])
                 + __bfloat162float(g_VTl[(size_t)c*DM + d]);
        mv = fmaxf(mv, vt);
    }
    g_mfin[b*DM + d] = mv;
    if (d < 64) g_fid[b*64 + d] = ids[b*SLOTS + g_fslot[b*64 + d]];
}

// ---------------------------------------------------------------------------
// Output head + flatten
// ---------------------------------------------------------------------------
__global__ void out_k(const float* __restrict__ ow, const float* __restrict__ ob,
                      float* __restrict__ out, int out_size)
{
    int tid = threadIdx.x;
    if (tid < 32) {
        int b = tid >> 1, o = tid & 1;
        float v = ob[o];
        for (int d = 0; d < DM; d++) v = fmaf(g_vfin[b*DM + d], ow[d*2 + o], v);
        for (int d = 0; d < DM; d++) v = fmaf(g_mfin[b*DM + d], ow[(DM + d)*2 + o], v);
        if (tid < out_size) out[tid] = v;
    }
    for (int i = tid; i < BSZ*64; i += blockDim.x)
        if (32 + i < out_size) out[32 + i] = (float)g_fid[i];
    for (int i = 32 + BSZ*64 + tid; i < out_size; i += blockDim.x)
        out[i] = 0.f;
}

// ---------------------------------------------------------------------------
// Launch
// ---------------------------------------------------------------------------
extern "C" void kernel_launch(void* const* d_in, const int* in_sizes, int n_in,
                              void* d_out, int out_size)
{
    const float* v_all  = (const float*)d_in[0];
    const float* tv_all = (const float*)d_in[1];
    const float* emb    = (const float*)d_in[2];
    const float* w1     = (const float*)d_in[3];
    const float* b1     = (const float*)d_in[4];
    const float* w2     = (const float*)d_in[5];
    const float* b2     = (const float*)d_in[6];
    const float* gam    = (const float*)d_in[7];
    const float* bet    = (const float*)d_in[8];
    const float* wq     = (const float*)d_in[9];
    const float* wk     = (const float*)d_in[10];
    const float* amw1   = (const float*)d_in[11];
    const float* amb1   = (const float*)d_in[12];
    const float* amw2   = (const float*)d_in[13];
    const float* ow     = (const float*)d_in[14];
    const float* ob     = (const float*)d_in[15];
    const int*   itxt   = (const int*)d_in[16];
    const int*   mtxt   = (const int*)d_in[17];
    const int*   lens   = (const int*)d_in[18];
    float* out = (float*)d_out;

    bf16 *pHh, *pHl, *pVTh, *pVTl, *pBh, *pBl;
    float *pKV, *pS2;
    int *pU, *pUL;
    cudaGetSymbolAddress((void**)&pHh,  g_Hh);
    cudaGetSymbolAddress((void**)&pHl,  g_Hl);
    cudaGetSymbolAddress((void**)&pVTh, g_VTh);
    cudaGetSymbolAddress((void**)&pVTl, g_VTl);
    cudaGetSymbolAddress((void**)&pKV,  g_KV);
    cudaGetSymbolAddress((void**)&pS2,  g_S2);
    cudaGetSymbolAddress((void**)&pBh,  g_Bh);
    cudaGetSymbolAddress((void**)&pBl,  g_Bl);
    cudaGetSymbolAddress((void**)&pU,   g_ucnt);
    cudaGetSymbolAddress((void**)&pUL,  g_ulist);

    cudaFuncSetAttribute(gemm_bf, cudaFuncAttributeMaxDynamicSharedMemorySize, GEMM_SMEM);

    // dedup + weight split
    prep0_k<<<640, 256>>>(w1, w2, wk, amw1 + DM*DM);
    mark_k<<<NTOK/256, 256>>>(itxt);
    scan1_k<<<64, 1024>>>();
    scan3_k<<<64, 1024>>>();

    // GEMM1: relu(emb[gather] @ w1 + b1) -> bf16 planes g_Hh/g_Hl
    gemm_bf<<<dim3(NVOC/128, 2), 512, GEMM_SMEM>>>(
        emb, nullptr, nullptr,
        pBh + OFF_W1, pBl + OFF_W1, nullptr, b1,
        nullptr, nullptr, nullptr, nullptr,
        KD, DH, pUL, 1, pU, 0, pHh, pHl, nullptr, nullptr, 0);

    tokc_k<<<NTOK/256, 256>>>(itxt);
    prep_k<<<NBL, DM>>>(v_all, tv_all, amw1, amb1, wq);

    // GEMM2 + fused LayerNorm: VT = LN(Hplanes @ w2 + b2) -> g_VTh/g_VTl
    gemm_bf<<<dim3(NVOC/128, 1), 512, GEMM_SMEM>>>(
        nullptr, pHh, pHl,
        pBh + OFF_W2, pBl + OFF_W2, nullptr, b2,
        nullptr, nullptr, nullptr, nullptr,
        DH, DM, nullptr, 0, pU, 0, pVTh, pVTl, gam, bet, 1);

    // GEMM3+4 fused: KV = VT @ wk ; S2 = VT @ am_w1[D:]
    gemm_bf<<<dim3(NVOC/128, 2), 512, GEMM_SMEM>>>(
        nullptr, pVTh, pVTl,
        pBh + OFF_WK, pBl + OFF_WK, pKV, nullptr,
        pBh + OFF_AM, pBl + OFF_AM, pS2, nullptr,
        DM, DM, nullptr, 0, pU, 1, nullptr, nullptr, nullptr, nullptr, 0);

    // fused score+selection, recurrence, pooling, head
    scorsel_k<<<NBL, 256>>>(amw2, mtxt);
    recur_k<<<BSZ, 256>>>(itxt, mtxt, lens);
    final_k<<<BSZ, DM>>>(tv_all, itxt, lens);
    out_k<<<1, 256>>>(ow, ob, out, out_size);
}

// round 16
// speedup vs baseline: 1.1277x; 1.0660x over previous
#include <cuda_runtime.h>
#include <cuda_bf16.h>
#include <math.h>
#include <stdint.h>

// ---------------------------------------------------------------------------
// Problem constants
// ---------------------------------------------------------------------------
#define BSZ   16
#define LSEQ  50
#define NBLK  64
#define DM    256
#define DH    512
#define KD    768
#define NVOC  65536
#define NTOK  (BSZ*LSEQ*NBLK)   // 51200
#define NBL   (BSZ*LSEQ)        // 800
#define SLOTS (LSEQ*NBLK)       // 3200 per batch

typedef __nv_bfloat16 bf16;

__device__ __forceinline__ float neg_inf() { return __int_as_float(0xff800000); }

// ---------------------------------------------------------------------------
// Scratch (static device globals; no allocation)
// ---------------------------------------------------------------------------
__device__ __align__(128) bf16  g_Hh[(size_t)NVOC*DH];  // relu hidden, bf16-hi
__device__ __align__(128) bf16  g_Hl[(size_t)NVOC*DH];  // relu hidden, bf16-lo
__device__ __align__(128) bf16  g_VTh[(size_t)NVOC*DM]; // v_text hi (post-LN)
__device__ __align__(128) bf16  g_VTl[(size_t)NVOC*DM]; // v_text lo (post-LN)
__device__ __align__(128) float g_KV[(size_t)NVOC*DM];  // v_text @ wk
__device__ __align__(128) float g_S2[(size_t)NVOC*DM];  // v_text @ am_w1[D:]
__device__ __align__(128) float g_T [NBL*DM];
__device__ __align__(128) float g_QW[NBL*DM];

// pre-split TRANSPOSED weight planes ([N][K], k-contiguous): w1 | w2 | wk | am
#define OFF_W1 0
#define OFF_W2 393216
#define OFF_WK 524288
#define OFF_AM 589824
#define TOTW   655360
__device__ __align__(128) bf16 g_Bh[TOTW];
__device__ __align__(128) bf16 g_Bl[TOTW];

__device__ int   g_present[NVOC];
__device__ int   g_cidx[NVOC];
__device__ int   g_ulist[NVOC];
__device__ int   g_bsum[64];
__device__ int   g_ucnt[1];
__device__ int   g_tokc[NTOK];
__device__ int   g_selslot[NTOK];
__device__ int   g_fslot[BSZ*64];
__device__ int   g_fid  [BSZ*64];
__device__ __align__(128) float g_vfin[BSZ*DM];
__device__ __align__(128) float g_mfin[BSZ*DM];

// ---------------------------------------------------------------------------
// helpers
// ---------------------------------------------------------------------------
__device__ __forceinline__ void split_bf(float x, bf16& h, bf16& l)
{
    h = __float2bfloat16_rn(x);
    l = __float2bfloat16_rn(x - __bfloat162float(h));
}
__device__ __forceinline__ uint32_t pack2(bf16 a, bf16 b)
{
    return (uint32_t)__bfloat16_as_ushort(a) | ((uint32_t)__bfloat16_as_ushort(b) << 16);
}
__device__ __forceinline__ void mma_bf16(float c[4], const uint32_t a[4],
                                         uint32_t b0, uint32_t b1)
{
    asm volatile(
        "mma.sync.aligned.m16n8k16.row.col.f32.bf16.bf16.f32 "
        "{%0,%1,%2,%3}, {%4,%5,%6,%7}, {%8,%9}, {%0,%1,%2,%3};"
        : "+f"(c[0]), "+f"(c[1]), "+f"(c[2]), "+f"(c[3])
        : "r"(a[0]), "r"(a[1]), "r"(a[2]), "r"(a[3]), "r"(b0), "r"(b1));
}
__device__ __forceinline__ void ldsm_x4(uint32_t r[4], uint32_t saddr)
{
    asm volatile("ldmatrix.sync.aligned.m8n8.x4.shared.b16 {%0,%1,%2,%3}, [%4];"
        : "=r"(r[0]), "=r"(r[1]), "=r"(r[2]), "=r"(r[3]) : "r"(saddr));
}
__device__ __forceinline__ uint32_t s2u(const void* p)
{
    return (uint32_t)__cvta_generic_to_shared(p);
}
__device__ __forceinline__ void cpasync16(uint32_t dst, const void* src)
{
    asm volatile("cp.async.ca.shared.global [%0], [%1], 16;" :: "r"(dst), "l"(src));
}
#define CP_COMMIT() asm volatile("cp.async.commit_group;")
#define CP_WAIT0()  asm volatile("cp.async.wait_group 0;")

// ---------------------------------------------------------------------------
// Launch 0: zero present/ulist + tiled transpose-split of all weights
// ---------------------------------------------------------------------------
__global__ void prep0_k(const float* __restrict__ w1, const float* __restrict__ w2,
                        const float* __restrict__ wk, const float* __restrict__ am1)
{
    int bid = blockIdx.x, tid = threadIdx.x;
    if (bid < 256) g_present[bid*256 + tid] = 0;
    else if (bid < 512) g_ulist[(bid-256)*256 + tid] = 0;

    const float* W; bf16 *oh, *ol; int K, N, kt, nt;
    int id = bid;
    if (id < 384)      { W = w1;  oh = g_Bh+OFF_W1; ol = g_Bl+OFF_W1; K = KD; N = DH; kt = id % 24; nt = id / 24; }
    else if (id < 512) { id -= 384; W = w2;  oh = g_Bh+OFF_W2; ol = g_Bl+OFF_W2; K = DH; N = DM; kt = id % 16; nt = id / 16; }
    else if (id < 576) { id -= 512; W = wk;  oh = g_Bh+OFF_WK; ol = g_Bl+OFF_WK; K = DM; N = DM; kt = id % 8;  nt = id / 8; }
    else               { id -= 576; W = am1; oh = g_Bh+OFF_AM; ol = g_Bl+OFF_AM; K = DM; N = DM; kt = id % 8;  nt = id / 8; }

    __shared__ float t[32][33];
    int tx = tid & 31, ty = tid >> 5;
#pragma unroll
    for (int i = 0; i < 4; i++) {
        int k = kt*32 + ty + i*8, n = nt*32 + tx;
        t[ty + i*8][tx] = W[(size_t)k*N + n];
    }
    __syncthreads();
#pragma unroll
    for (int i = 0; i < 4; i++) {
        int n = nt*32 + ty + i*8, k = kt*32 + tx;
        split_bf(t[tx][ty + i*8], oh[(size_t)n*K + k], ol[(size_t)n*K + k]);
    }
}
__global__ void mark_k(const int* __restrict__ ids)
{
    int t = blockIdx.x * blockDim.x + threadIdx.x;
    if (t < NTOK) g_present[ids[t]] = 1;
}
__global__ void scan1_k()
{
    __shared__ int s[1024];
    int t = threadIdx.x, g = blockIdx.x * 1024 + t;
    int p = g_present[g];
    s[t] = p; __syncthreads();
    for (int off = 1; off < 1024; off <<= 1) {
        int v = (t >= off) ? s[t - off] : 0;
        __syncthreads();
        s[t] += v;
        __syncthreads();
    }
    g_cidx[g] = s[t] - p;
    if (t == 1023) g_bsum[blockIdx.x] = s[t];
}
__global__ void scan3_k()
{
    __shared__ int off_s;
    int t = threadIdx.x, g = blockIdx.x * 1024 + t;
    if (t == 0) {
        int run = 0;
        for (int i = 0; i < (int)blockIdx.x; i++) run += g_bsum[i];
        off_s = run;
        if (blockIdx.x == 63) g_ucnt[0] = run + g_bsum[63];
    }
    __syncthreads();
    int c = g_cidx[g] + off_s;
    g_cidx[g] = c;
    if (g_present[g]) g_ulist[c] = g;
}
__global__ void tokc_k(const int* __restrict__ ids)
{
    int t = blockIdx.x * blockDim.x + threadIdx.x;
    if (t < NTOK) g_tokc[t] = g_cidx[ids[t]];
}

// ---------------------------------------------------------------------------
// BF16 3-product split GEMM (h*h + l*h + h*l), fp32 accumulate.
// Block 128x256, BK=32, 512 threads (16 warps, 4m x 4n, warp tile 32x64).
// PROVEN 2-stage double buffer. ldmatrix.x4; pass-major MMA; fixed hh,lh,hl
// per-k16 accumulation => deterministic per gathered row.
// ilv: 1-D grid with y interleaved in bit 0 of blockIdx.x so the two CTAs
// sharing an A-row block run adjacently (L2 temporal reuse of gathered A).
// fuse_ln: full-row LayerNorm epilogue, emit bf16 hi/lo planes.
// ---------------------------------------------------------------------------
#define A_STRB 40
#define A_PL   (128*A_STRB)                 // 5120 bf16
#define B_PL   (256*A_STRB)                 // 10240 bf16
#define BUF_E  (2*A_PL + 2*B_PL)            // 30720 bf16
#define BUF_B  (BUF_E*2)                    // 61440 bytes
#define GEMM_SMEM (2*BUF_B)                 // 122880 bytes

__global__ void __launch_bounds__(512, 1) gemm_bf(
    const float* __restrict__ Araw,
    const bf16* __restrict__ AhG, const bf16* __restrict__ AlG,
    const bf16* __restrict__ Bh0, const bf16* __restrict__ Bl0,
    float* __restrict__ C0, const float* __restrict__ bias0,
    const bf16* __restrict__ Bh1, const bf16* __restrict__ Bl1,
    float* __restrict__ C1, const float* __restrict__ bias1,
    int Kdim, int Ndim,
    const int* __restrict__ gather,
    int act,
    const int* __restrict__ ucntp,
    int dual,
    bf16* __restrict__ Ch, bf16* __restrict__ Cl,
    const float* __restrict__ lng, const float* __restrict__ lnb,
    int fuse_ln, int ilv)
{
    extern __shared__ bf16 smbf[];
    int bxm, yv;
    if (ilv) { bxm = blockIdx.x >> 1; yv = blockIdx.x & 1; }
    else     { bxm = blockIdx.x;      yv = 0; }
    const int bm = bxm * 128;
    if (bm >= ucntp[0]) return;

    const bf16 *BhG, *BlG;
    const float* bias_;
    float* Cp;
    int bn;
    if (dual && yv) { BhG = Bh1; BlG = Bl1; Cp = C1; bias_ = bias1; bn = 0; }
    else { BhG = Bh0; BlG = Bl0; Cp = C0; bias_ = bias0; bn = dual ? 0 : yv * 256; }

    const int tid = threadIdx.x;
    const int wid = tid >> 5, lane = tid & 31;
    const int wm = (wid >> 2) * 32, wn = (wid & 3) * 64;
    const int grp = lane >> 2, qd = lane & 3;

    const int fa_row = tid >> 2, fa_q = tid & 3;
    const int fb_row = tid >> 1, fb_h = tid & 1;

    int ar = bm + fa_row;
    if (gather) ar = gather[ar];
    const bool gatherA = (Araw != nullptr);
    const float* ApR = gatherA ? (Araw + (size_t)ar * Kdim + fa_q * 8) : nullptr;
    const bf16* AhR = gatherA ? nullptr : (AhG + (size_t)(bm + fa_row) * Kdim + fa_q * 8);
    const bf16* AlR = gatherA ? nullptr : (AlG + (size_t)(bm + fa_row) * Kdim + fa_q * 8);
    const bf16* BhR = BhG + (size_t)(bn + fb_row) * Kdim;
    const bf16* BlR = BlG + (size_t)(bn + fb_row) * Kdim;

    float acc[2][8][4];
#pragma unroll
    for (int mi = 0; mi < 2; mi++)
#pragma unroll
        for (int ni = 0; ni < 8; ni++)
#pragma unroll
            for (int j = 0; j < 4; j++) acc[mi][ni][j] = 0.f;

    const int ktiles = Kdim >> 5;

    const uint32_t smBase = s2u(smbf);
    const uint32_t aFrag = (uint32_t)((wm + (lane & 15)) * (A_STRB*2)) + ((lane >> 4) * 16);
    const uint32_t bFrag = (uint32_t)(2*A_PL*2) +
        (uint32_t)((wn + (lane & 7) + ((lane >> 4) & 1) * 8) * (A_STRB*2)) +
        (((lane >> 3) & 1) * 16);

    auto issueB = [&](int bufo, int kt) {
        uint32_t dh = smBase + bufo + 2*A_PL*2 + (fb_row*A_STRB + fb_h*16) * 2;
        uint32_t dl = dh + B_PL*2;
        const bf16* sh = BhR + kt*32 + fb_h*16;
        const bf16* sl = BlR + kt*32 + fb_h*16;
        cpasync16(dh,      sh);
        cpasync16(dh + 16, sh + 8);
        cpasync16(dl,      sl);
        cpasync16(dl + 16, sl + 8);
    };
    auto issueA = [&](int bufo, int kt) {
        uint32_t dh = smBase + bufo + (fa_row*A_STRB + fa_q*8) * 2;
        cpasync16(dh,            AhR + kt*32);
        cpasync16(dh + A_PL*2,   AlR + kt*32);
    };
    auto stageAgather = [&](int bufo, int kt) {
        float4 v0 = *(const float4*)(ApR + kt*32);
        float4 v1 = *(const float4*)(ApR + kt*32 + 4);
        bf16 h[8], l[8];
        split_bf(v0.x, h[0], l[0]); split_bf(v0.y, h[1], l[1]);
        split_bf(v0.z, h[2], l[2]); split_bf(v0.w, h[3], l[3]);
        split_bf(v1.x, h[4], l[4]); split_bf(v1.y, h[5], l[5]);
        split_bf(v1.z, h[6], l[6]); split_bf(v1.w, h[7], l[7]);
        uint32_t off = bufo + (fa_row*A_STRB + fa_q*8) * 2;
        uint4 ph = make_uint4(pack2(h[0],h[1]), pack2(h[2],h[3]),
                              pack2(h[4],h[5]), pack2(h[6],h[7]));
        uint4 pl = make_uint4(pack2(l[0],l[1]), pack2(l[2],l[3]),
                              pack2(l[4],l[5]), pack2(l[6],l[7]));
        *(uint4*)((char*)smbf + off)           = ph;
        *(uint4*)((char*)smbf + off + A_PL*2)  = pl;
    };

    // prologue: stage 0 -> buffer 0
    issueB(0, 0);
    if (gatherA) stageAgather(0, 0); else issueA(0, 0);
    CP_COMMIT(); CP_WAIT0();
    __syncthreads();

    for (int kt = 0; kt < ktiles; kt++) {
        const int curo = (kt & 1) * BUF_B;
        const int nxto = curo ^ BUF_B;
        const bool more = (kt + 1 < ktiles);
        if (more) {
            issueB(nxto, kt + 1);
            if (gatherA) stageAgather(nxto, kt + 1); else issueA(nxto, kt + 1);
            CP_COMMIT();
        }

#pragma unroll
        for (int k16 = 0; k16 < 2; k16++) {
            uint32_t aH[2][4], aL[2][4];
#pragma unroll
            for (int mi = 0; mi < 2; mi++) {
                uint32_t addr = smBase + curo + aFrag + mi*16*(A_STRB*2) + k16*32;
                ldsm_x4(aH[mi], addr);
                ldsm_x4(aL[mi], addr + A_PL*2);
            }
#pragma unroll
            for (int nig = 0; nig < 4; nig++) {
                uint32_t bH[4], bL[4];
                uint32_t addr = smBase + curo + bFrag + nig*16*(A_STRB*2) + k16*32;
                ldsm_x4(bH, addr);
                ldsm_x4(bL, addr + B_PL*2);
#pragma unroll
                for (int s = 0; s < 2; s++)
#pragma unroll
                    for (int mi = 0; mi < 2; mi++)
                        mma_bf16(acc[mi][nig*2+s], aH[mi], bH[2*s], bH[2*s+1]);
#pragma unroll
                for (int s = 0; s < 2; s++)
#pragma unroll
                    for (int mi = 0; mi < 2; mi++)
                        mma_bf16(acc[mi][nig*2+s], aL[mi], bH[2*s], bH[2*s+1]);
#pragma unroll
                for (int s = 0; s < 2; s++)
#pragma unroll
                    for (int mi = 0; mi < 2; mi++)
                        mma_bf16(acc[mi][nig*2+s], aH[mi], bL[2*s], bL[2*s+1]);
            }
        }

        if (more) CP_WAIT0();
        __syncthreads();
    }

    if (!fuse_ln) {
#pragma unroll
        for (int mi = 0; mi < 2; mi++) {
            const int r0 = bm + wm + mi*16 + grp;
#pragma unroll
            for (int ni = 0; ni < 8; ni++) {
                const int n = bn + wn + ni*8 + qd*2;
                float b0 = bias_ ? bias_[n]   : 0.f;
                float b1 = bias_ ? bias_[n+1] : 0.f;
                float v0 = acc[mi][ni][0] + b0, v1 = acc[mi][ni][1] + b1;
                float v2 = acc[mi][ni][2] + b0, v3 = acc[mi][ni][3] + b1;
                if (act == 1) {
                    v0 = fmaxf(v0, 0.f); v1 = fmaxf(v1, 0.f);
                    v2 = fmaxf(v2, 0.f); v3 = fmaxf(v3, 0.f);
                }
                if (Cp) {
                    *(float2*)&Cp[(size_t)r0 * Ndim + n]     = make_float2(v0, v1);
                    *(float2*)&Cp[(size_t)(r0+8) * Ndim + n] = make_float2(v2, v3);
                }
                if (Ch) {
                    bf16 h0,l0,h1,l1,h2,l2,h3,l3;
                    split_bf(v0,h0,l0); split_bf(v1,h1,l1);
                    split_bf(v2,h2,l2); split_bf(v3,h3,l3);
                    *(uint32_t*)&Ch[(size_t)r0 * Ndim + n]     = pack2(h0, h1);
                    *(uint32_t*)&Ch[(size_t)(r0+8) * Ndim + n] = pack2(h2, h3);
                    *(uint32_t*)&Cl[(size_t)r0 * Ndim + n]     = pack2(l0, l1);
                    *(uint32_t*)&Cl[(size_t)(r0+8) * Ndim + n] = pack2(l2, l3);
                }
            }
        }
    } else {
        float* red = (float*)smbf;          // [128][17] padded
        float* mus = red + 128*17;
        float* sis = mus + 128;
        const int slot = (wid & 3)*4 + qd;

#pragma unroll
        for (int mi = 0; mi < 2; mi++) {
            const int lr = wm + mi*16 + grp;
            float s0 = 0.f, s1 = 0.f;
#pragma unroll
            for (int ni = 0; ni < 8; ni++) {
                const int n = wn + ni*8 + qd*2;
                float b0 = bias_[n], b1 = bias_[n+1];
                acc[mi][ni][0] += b0; acc[mi][ni][1] += b1;
                acc[mi][ni][2] += b0; acc[mi][ni][3] += b1;
                s0 += acc[mi][ni][0] + acc[mi][ni][1];
                s1 += acc[mi][ni][2] + acc[mi][ni][3];
            }
            red[lr*17 + slot]     = s0;
            red[(lr+8)*17 + slot] = s1;
        }
        __syncthreads();
        if (tid < 128) {
            float m = 0.f;
#pragma unroll
            for (int s = 0; s < 16; s++) m += red[tid*17 + s];
            mus[tid] = m * (1.f/DM);
        }
        __syncthreads();
#pragma unroll
        for (int mi = 0; mi < 2; mi++) {
            const int lr = wm + mi*16 + grp;
            float mu0 = mus[lr], mu1 = mus[lr+8];
            float s0 = 0.f, s1 = 0.f;
#pragma unroll
            for (int ni = 0; ni < 8; ni++) {
                float c0 = acc[mi][ni][0]-mu0, c1 = acc[mi][ni][1]-mu0;
                float c2 = acc[mi][ni][2]-mu1, c3 = acc[mi][ni][3]-mu1;
                s0 += c0*c0 + c1*c1;
                s1 += c2*c2 + c3*c3;
            }
            red[lr*17 + slot]     = s0;
            red[(lr+8)*17 + slot] = s1;
        }
        __syncthreads();
        if (tid < 128) {
            float v = 0.f;
#pragma unroll
            for (int s = 0; s < 16; s++) v += red[tid*17 + s];
            sis[tid] = rsqrtf(v * (1.f/DM) + 1e-5f);
        }
        __syncthreads();
#pragma unroll
        for (int mi = 0; mi < 2; mi++) {
            const int lr = wm + mi*16 + grp;
            const int r0 = bm + lr;
            float mu0 = mus[lr], is0 = sis[lr];
            float mu1 = mus[lr+8], is1 = sis[lr+8];
#pragma unroll
            for (int ni = 0; ni < 8; ni++) {
                const int n = wn + ni*8 + qd*2;
                float g0 = lng[n], g1 = lng[n+1], e0 = lnb[n], e1 = lnb[n+1];
                float v0 = g0*(acc[mi][ni][0]-mu0)*is0 + e0;
                float v1 = g1*(acc[mi][ni][1]-mu0)*is0 + e1;
                float v2 = g0*(acc[mi][ni][2]-mu1)*is1 + e0;
                float v3 = g1*(acc[mi][ni][3]-mu1)*is1 + e1;
                bf16 h0,l0,h1,l1,h2,l2,h3,l3;
                split_bf(v0,h0,l0); split_bf(v1,h1,l1);
                split_bf(v2,h2,l2); split_bf(v3,h3,l3);
                *(uint32_t*)&Ch[(size_t)r0 * Ndim + n]     = pack2(h0, h1);
                *(uint32_t*)&Ch[(size_t)(r0+8) * Ndim + n] = pack2(h2, h3);
                *(uint32_t*)&Cl[(size_t)r0 * Ndim + n]     = pack2(l0, l1);
                *(uint32_t*)&Cl[(size_t)(r0+8) * Ndim + n] = pack2(l2, l3);
            }
        }
    }
}

// ---------------------------------------------------------------------------
// Per-(b,l) precompute
// ---------------------------------------------------------------------------
__global__ void prep_k(const float* __restrict__ v, const float* __restrict__ tv,
                       const float* __restrict__ am_w1, const float* __restrict__ am_b1,
                       const float* __restrict__ wq)
{
    __shared__ float tvs[DM];
    __shared__ float qs[DM];
    int bl = blockIdx.x, d = threadIdx.x;
    float t0 = tv[(size_t)bl*DM + d];
    tvs[d] = t0;
    qs[d]  = t0 + v[(size_t)bl*DM + d];
    __syncthreads();
    float t = am_b1[d], q = 0.f;
    for (int k = 0; k < DM; k++) {
        t = fmaf(tvs[k], am_w1[k*DM + d], t);
        q = fmaf(qs[k],  wq  [k*DM + d], q);
    }
    g_T [(size_t)bl*DM + d] = t;
    g_QW[(size_t)bl*DM + d] = q;
}

// ---------------------------------------------------------------------------
// Fused per-visit score + stable sort (one block per (b,l) visit).
// Same lane-strided float4 accumulation order => bitwise-identical scores.
// ---------------------------------------------------------------------------
__global__ void scorsel_k(const float* __restrict__ am_w2,
                          const int* __restrict__ masks)
{
    int bl = blockIdx.x;
    int tid = threadIdx.x, wid = tid >> 5, lane = tid & 31;
    __shared__ float key[64];

    const float4* tt4 = (const float4*)(g_T + (size_t)bl * DM);
    const float4* w4  = (const float4*)am_w2;
    float4 t0 = tt4[lane*2], t1 = tt4[lane*2+1];
    float4 w0 = w4[lane*2],  w1 = w4[lane*2+1];

#pragma unroll
    for (int i = 0; i < 8; i++) {
        int j = wid*8 + i;
        int tok = bl*64 + j;
        int c = g_tokc[tok];
        const float4* s24 = (const float4*)(g_S2 + (size_t)c * DM);
        float4 a0 = s24[lane*2], a1 = s24[lane*2+1];
        float s = 0.f;
        s = fmaf(tanhf(a0.x + t0.x), w0.x, s);
        s = fmaf(tanhf(a0.y + t0.y), w0.y, s);
        s = fmaf(tanhf(a0.z + t0.z), w0.z, s);
        s = fmaf(tanhf(a0.w + t0.w), w0.w, s);
        s = fmaf(tanhf(a1.x + t1.x), w1.x, s);
        s = fmaf(tanhf(a1.y + t1.y), w1.y, s);
        s = fmaf(tanhf(a1.z + t1.z), w1.z, s);
        s = fmaf(tanhf(a1.w + t1.w), w1.w, s);
        for (int o = 16; o > 0; o >>= 1) s += __shfl_down_sync(0xffffffffu, s, o);
        if (lane == 0) key[j] = masks[tok] ? s : neg_inf();
    }
    __syncthreads();

    if (tid < 64) {
        int j = tid;
        float k_ = key[j];
        int rank = 0;
        for (int m = 0; m < 64; m++) {
            float o = key[m];
            rank += (o > k_) || (o == k_ && m < j);
        }
        g_selslot[bl*64 + rank] = (bl % LSEQ) * NBLK + j;
    }
}

// ---------------------------------------------------------------------------
// Sequential memory recurrence. Batch-resident smem: all q vectors (50x256)
// plus per-batch selslot/masks/tokc preloaded once (dynamic smem ~90KB),
// removing per-step gmem latency from the 49-step serial chain.
// Half-warp per candidate + float4 rank scan (numerics identical to r15).
// ---------------------------------------------------------------------------
#define RECUR_SMEM ((LSEQ*DM)*4 + 3*SLOTS*4)   // 51200*4? no: floats+ints bytes

__global__ void recur_k(const int* __restrict__ ids, const int* __restrict__ masks,
                        const int* __restrict__ lens)
{
    extern __shared__ float dsm[];
    float* qall  = dsm;                          // LSEQ*DM floats
    int*   sel_s = (int*)(qall + LSEQ*DM);       // SLOTS
    int*   msk_s = sel_s + SLOTS;                // SLOTS
    int*   tok_s = msk_s + SLOTS;                // SLOTS

    int b = blockIdx.x, tid = threadIdx.x;
    __shared__ int cslot[64], cmask[64];
    __shared__ int nslot[64], nmask[64];
    __shared__ int dslot[128], dmask[128], dcid[128];
    __shared__ float ev[128];
    __shared__ __align__(16) float mk[128];

    // batch-resident preload
    {
        const float4* src = (const float4*)(g_QW + (size_t)b * LSEQ * DM);
        float4* dst = (float4*)qall;
        for (int i = tid; i < LSEQ*DM/4; i += 256) dst[i] = src[i];
        const int4* ss = (const int4*)(g_selslot + b * SLOTS);
        const int4* ms = (const int4*)(masks + b * SLOTS);
        const int4* ts = (const int4*)(g_tokc + b * SLOTS);
        for (int i = tid; i < SLOTS/4; i += 256) {
            ((int4*)sel_s)[i] = ss[i];
            ((int4*)msk_s)[i] = ms[i];
            ((int4*)tok_s)[i] = ts[i];
        }
    }
    int lb = lens[b];
    __syncthreads();

    if (tid < 64) {
        int slot = sel_s[0*64 + tid];
        cslot[tid] = slot;
        cmask[tid] = msk_s[slot];
    }
    __syncthreads();

    const int hw = tid >> 4, hl = tid & 15;

    for (int t = 1; t < LSEQ; t++) {
        if (tid < 128) {
            int slot = (tid < 64) ? cslot[tid] : sel_s[t*64 + (tid - 64)];
            dslot[tid] = slot;
            dmask[tid] = (tid < 64) ? cmask[tid] : msk_s[slot];
            dcid [tid] = tok_s[slot];
        }
        __syncthreads();

        const float4* q4 = (const float4*)(qall + (size_t)t * DM);
        float4 qv0 = q4[hl], qv1 = q4[hl+16], qv2 = q4[hl+32], qv3 = q4[hl+48];
        const float4* kv = (const float4*)(g_KV + (size_t)dcid[hw] * DM);
        float4 k0 = kv[hl], k1 = kv[hl+16], k2 = kv[hl+32], k3 = kv[hl+48];
        for (int c = hw; c < 128; c += 16) {
            const bool hasnext = (c + 16 < 128);
            float4 n0, n1, n2, n3;
            if (hasnext) {
                const float4* kn = (const float4*)(g_KV + (size_t)dcid[c + 16] * DM);
                n0 = kn[hl]; n1 = kn[hl+16]; n2 = kn[hl+32]; n3 = kn[hl+48];
            }
            float s = k0.x*qv0.x + k0.y*qv0.y + k0.z*qv0.z + k0.w*qv0.w
                    + k1.x*qv1.x + k1.y*qv1.y + k1.z*qv1.z + k1.w*qv1.w
                    + k2.x*qv2.x + k2.y*qv2.y + k2.z*qv2.z + k2.w*qv2.w
                    + k3.x*qv3.x + k3.y*qv3.y + k3.z*qv3.z + k3.w*qv3.w;
            for (int o = 8; o > 0; o >>= 1) s += __shfl_down_sync(0xffffffffu, s, o, 16);
            if (hl == 0) ev[c] = s;
            if (hasnext) { k0 = n0; k1 = n1; k2 = n2; k3 = n3; }
        }
        __syncthreads();

        if (tid < 128) mk[tid] = dmask[tid] ? ev[tid] : neg_inf();
        __syncthreads();

        if (tid < 128) {
            float k_ = mk[tid];
            int rank = 0;
            const float4* m4 = (const float4*)mk;
#pragma unroll 8
            for (int i = 0; i < 32; i++) {
                float4 o4 = m4[i];
                int mb = i*4;
                rank += (o4.x > k_) || (o4.x == k_ && mb+0 < tid);
                rank += (o4.y > k_) || (o4.y == k_ && mb+1 < tid);
                rank += (o4.z > k_) || (o4.z == k_ && mb+2 < tid);
                rank += (o4.w > k_) || (o4.w == k_ && mb+3 < tid);
            }
            if (rank < 64) { nslot[rank] = dslot[tid]; nmask[rank] = dmask[tid]; }
        }
        __syncthreads();
        if (tid < 64) {
            cslot[tid] = nslot[tid];
            cmask[tid] = nmask[tid];
            if (t == lb - 1) g_fslot[b*64 + tid] = nslot[tid];
        }
        __syncthreads();
    }
}

// ---------------------------------------------------------------------------
// Pools (VT reconstructed as hi+lo; max-pool path, 1e-3 tolerance)
// ---------------------------------------------------------------------------
__global__ void final_k(const float* __restrict__ tv, const int* __restrict__ ids,
                        const int* __restrict__ lens)
{
    int b = blockIdx.x, d = threadIdx.x;
    int lb = lens[b];
    float mx = neg_inf();
    for (int l = 0; l < lb; l++) mx = fmaxf(mx, tv[((size_t)b*LSEQ + l)*DM + d]);
    g_vfin[b*DM + d] = mx;
    float mv = neg_inf();
    for (int m = 0; m < 64; m++) {
        int c = g_tokc[b*SLOTS + g_fslot[b*64 + m]];
        float vt = __bfloat162float(g_VTh[(size_t)c*DM + d])
                 + __bfloat162float(g_VTl[(size_t)c*DM + d]);
        mv = fmaxf(mv, vt);
    }
    g_mfin[b*DM + d] = mv;
    if (d < 64) g_fid[b*64 + d] = ids[b*SLOTS + g_fslot[b*64 + d]];
}

// ---------------------------------------------------------------------------
// Output head + flatten
// ---------------------------------------------------------------------------
__global__ void out_k(const float* __restrict__ ow, const float* __restrict__ ob,
                      float* __restrict__ out, int out_size)
{
    int tid = threadIdx.x;
    if (tid < 32) {
        int b = tid >> 1, o = tid & 1;
        float v = ob[o];
        for (int d = 0; d < DM; d++) v = fmaf(g_vfin[b*DM + d], ow[d*2 + o], v);
        for (int d = 0; d < DM; d++) v = fmaf(g_mfin[b*DM + d], ow[(DM + d)*2 + o], v);
        if (tid < out_size) out[tid] = v;
    }
    for (int i = tid; i < BSZ*64; i += blockDim.x)
        if (32 + i < out_size) out[32 + i] = (float)g_fid[i];
    for (int i = 32 + BSZ*64 + tid; i < out_size; i += blockDim.x)
        out[i] = 0.f;
}

// ---------------------------------------------------------------------------
// Launch
// ---------------------------------------------------------------------------
extern "C" void kernel_launch(void* const* d_in, const int* in_sizes, int n_in,
                              void* d_out, int out_size)
{
    const float* v_all  = (const float*)d_in[0];
    const float* tv_all = (const float*)d_in[1];
    const float* emb    = (const float*)d_in[2];
    const float* w1     = (const float*)d_in[3];
    const float* b1     = (const float*)d_in[4];
    const float* w2     = (const float*)d_in[5];
    const float* b2     = (const float*)d_in[6];
    const float* gam    = (const float*)d_in[7];
    const float* bet    = (const float*)d_in[8];
    const float* wq     = (const float*)d_in[9];
    const float* wk     = (const float*)d_in[10];
    const float* amw1   = (const float*)d_in[11];
    const float* amb1   = (const float*)d_in[12];
    const float* amw2   = (const float*)d_in[13];
    const float* ow     = (const float*)d_in[14];
    const float* ob     = (const float*)d_in[15];
    const int*   itxt   = (const int*)d_in[16];
    const int*   mtxt   = (const int*)d_in[17];
    const int*   lens   = (const int*)d_in[18];
    float* out = (float*)d_out;

    bf16 *pHh, *pHl, *pVTh, *pVTl, *pBh, *pBl;
    float *pKV, *pS2;
    int *pU, *pUL;
    cudaGetSymbolAddress((void**)&pHh,  g_Hh);
    cudaGetSymbolAddress((void**)&pHl,  g_Hl);
    cudaGetSymbolAddress((void**)&pVTh, g_VTh);
    cudaGetSymbolAddress((void**)&pVTl, g_VTl);
    cudaGetSymbolAddress((void**)&pKV,  g_KV);
    cudaGetSymbolAddress((void**)&pS2,  g_S2);
    cudaGetSymbolAddress((void**)&pBh,  g_Bh);
    cudaGetSymbolAddress((void**)&pBl,  g_Bl);
    cudaGetSymbolAddress((void**)&pU,   g_ucnt);
    cudaGetSymbolAddress((void**)&pUL,  g_ulist);

    cudaFuncSetAttribute(gemm_bf, cudaFuncAttributeMaxDynamicSharedMemorySize, GEMM_SMEM);
    const int recur_smem = (LSEQ*DM)*4 + 3*SLOTS*4;   // 51200 + 38400 = 89600 B
    cudaFuncSetAttribute(recur_k, cudaFuncAttributeMaxDynamicSharedMemorySize, recur_smem);

    // dedup + weight split
    prep0_k<<<640, 256>>>(w1, w2, wk, amw1 + DM*DM);
    mark_k<<<NTOK/256, 256>>>(itxt);
    scan1_k<<<64, 1024>>>();
    scan3_k<<<64, 1024>>>();

    // GEMM1: relu(emb[gather] @ w1 + b1) -> bf16 planes (y-interleaved grid)
    gemm_bf<<<NVOC/64, 512, GEMM_SMEM>>>(
        emb, nullptr, nullptr,
        pBh + OFF_W1, pBl + OFF_W1, nullptr, b1,
        nullptr, nullptr, nullptr, nullptr,
        KD, DH, pUL, 1, pU, 0, pHh, pHl, nullptr, nullptr, 0, 1);

    tokc_k<<<NTOK/256, 256>>>(itxt);
    prep_k<<<NBL, DM>>>(v_all, tv_all, amw1, amb1, wq);

    // GEMM2 + fused LayerNorm: VT = LN(Hplanes @ w2 + b2) -> g_VTh/g_VTl
    gemm_bf<<<NVOC/128, 512, GEMM_SMEM>>>(
        nullptr, pHh, pHl,
        pBh + OFF_W2, pBl + OFF_W2, nullptr, b2,
        nullptr, nullptr, nullptr, nullptr,
        DH, DM, nullptr, 0, pU, 0, pVTh, pVTl, gam, bet, 1, 0);

    // GEMM3+4 fused: KV = VT @ wk ; S2 = VT @ am_w1[D:] (y-interleaved grid)
    gemm_bf<<<NVOC/64, 512, GEMM_SMEM>>>(
        nullptr, pVTh, pVTl,
        pBh + OFF_WK, pBl + OFF_WK, pKV, nullptr,
        pBh + OFF_AM, pBl + OFF_AM, pS2, nullptr,
        DM, DM, nullptr, 0, pU, 1, nullptr, nullptr, nullptr, nullptr, 0, 1);

    // fused score+selection, recurrence, pooling, head
    scorsel_k<<<NBL, 256>>>(amw2, mtxt);
    recur_k<<<BSZ, 256, recur_smem>>>(itxt, mtxt, lens);
    final_k<<<BSZ, DM>>>(tv_all, itxt, lens);
    out_k<<<1, 256>>>(ow, ob, out, out_size);
}

// round 17
// speedup vs baseline: 1.1416x; 1.0124x over previous
#include <cuda_runtime.h>
#include <cuda_bf16.h>
#include <math.h>
#include <stdint.h>

// ---------------------------------------------------------------------------
// Problem constants
// ---------------------------------------------------------------------------
#define BSZ   16
#define LSEQ  50
#define NBLK  64
#define DM    256
#define DH    512
#define KD    768
#define NVOC  65536
#define NTOK  (BSZ*LSEQ*NBLK)   // 51200
#define NBL   (BSZ*LSEQ)        // 800
#define SLOTS (LSEQ*NBLK)       // 3200 per batch

typedef __nv_bfloat16 bf16;

__device__ __forceinline__ float neg_inf() { return __int_as_float(0xff800000); }

// ---------------------------------------------------------------------------
// Scratch (static device globals; no allocation)
// ---------------------------------------------------------------------------
__device__ __align__(128) bf16  g_Hh[(size_t)NVOC*DH];  // relu hidden, bf16-hi
__device__ __align__(128) bf16  g_Hl[(size_t)NVOC*DH];  // relu hidden, bf16-lo
__device__ __align__(128) bf16  g_VTh[(size_t)NVOC*DM]; // v_text hi (post-LN)
__device__ __align__(128) bf16  g_VTl[(size_t)NVOC*DM]; // v_text lo (post-LN)
__device__ __align__(128) float g_KV[(size_t)NVOC*DM];  // v_text @ wk
__device__ __align__(128) float g_S2[(size_t)NVOC*DM];  // v_text @ am_w1[D:]
__device__ __align__(128) float g_T [NBL*DM];
__device__ __align__(128) float g_QW[NBL*DM];

// pre-split TRANSPOSED weight planes ([N][K], k-contiguous): w1 | w2 | wk | am
#define OFF_W1 0
#define OFF_W2 393216
#define OFF_WK 524288
#define OFF_AM 589824
#define TOTW   655360
__device__ __align__(128) bf16 g_Bh[TOTW];
__device__ __align__(128) bf16 g_Bl[TOTW];

__device__ int   g_present[NVOC];
__device__ int   g_cidx[NVOC];
__device__ int   g_ulist[NVOC];
__device__ int   g_bsum[64];
__device__ int   g_ucnt[1];
__device__ int   g_tokc[NTOK];
__device__ int   g_selslot[NTOK];
__device__ int   g_fslot[BSZ*64];
__device__ int   g_fid  [BSZ*64];
__device__ __align__(128) float g_vfin[BSZ*DM];
__device__ __align__(128) float g_mfin[BSZ*DM];

// ---------------------------------------------------------------------------
// helpers
// ---------------------------------------------------------------------------
__device__ __forceinline__ void split_bf(float x, bf16& h, bf16& l)
{
    h = __float2bfloat16_rn(x);
    l = __float2bfloat16_rn(x - __bfloat162float(h));
}
__device__ __forceinline__ uint32_t pack2(bf16 a, bf16 b)
{
    return (uint32_t)__bfloat16_as_ushort(a) | ((uint32_t)__bfloat16_as_ushort(b) << 16);
}
__device__ __forceinline__ void mma_bf16(float c[4], const uint32_t a[4],
                                         uint32_t b0, uint32_t b1)
{
    asm volatile(
        "mma.sync.aligned.m16n8k16.row.col.f32.bf16.bf16.f32 "
        "{%0,%1,%2,%3}, {%4,%5,%6,%7}, {%8,%9}, {%0,%1,%2,%3};"
        : "+f"(c[0]), "+f"(c[1]), "+f"(c[2]), "+f"(c[3])
        : "r"(a[0]), "r"(a[1]), "r"(a[2]), "r"(a[3]), "r"(b0), "r"(b1));
}
__device__ __forceinline__ void ldsm_x4(uint32_t r[4], uint32_t saddr)
{
    asm volatile("ldmatrix.sync.aligned.m8n8.x4.shared.b16 {%0,%1,%2,%3}, [%4];"
        : "=r"(r[0]), "=r"(r[1]), "=r"(r[2]), "=r"(r[3]) : "r"(saddr));
}
__device__ __forceinline__ uint32_t s2u(const void* p)
{
    return (uint32_t)__cvta_generic_to_shared(p);
}
__device__ __forceinline__ void cpasync16(uint32_t dst, const void* src)
{
    asm volatile("cp.async.ca.shared.global [%0], [%1], 16;" :: "r"(dst), "l"(src));
}
#define CP_COMMIT() asm volatile("cp.async.commit_group;")
#define CP_WAIT0()  asm volatile("cp.async.wait_group 0;")

// ---------------------------------------------------------------------------
// Launch 0: zero present/ulist + tiled transpose-split of all weights
// ---------------------------------------------------------------------------
__global__ void prep0_k(const float* __restrict__ w1, const float* __restrict__ w2,
                        const float* __restrict__ wk, const float* __restrict__ am1)
{
    int bid = blockIdx.x, tid = threadIdx.x;
    if (bid < 256) g_present[bid*256 + tid] = 0;
    else if (bid < 512) g_ulist[(bid-256)*256 + tid] = 0;

    const float* W; bf16 *oh, *ol; int K, N, kt, nt;
    int id = bid;
    if (id < 384)      { W = w1;  oh = g_Bh+OFF_W1; ol = g_Bl+OFF_W1; K = KD; N = DH; kt = id % 24; nt = id / 24; }
    else if (id < 512) { id -= 384; W = w2;  oh = g_Bh+OFF_W2; ol = g_Bl+OFF_W2; K = DH; N = DM; kt = id % 16; nt = id / 16; }
    else if (id < 576) { id -= 512; W = wk;  oh = g_Bh+OFF_WK; ol = g_Bl+OFF_WK; K = DM; N = DM; kt = id % 8;  nt = id / 8; }
    else               { id -= 576; W = am1; oh = g_Bh+OFF_AM; ol = g_Bl+OFF_AM; K = DM; N = DM; kt = id % 8;  nt = id / 8; }

    __shared__ float t[32][33];
    int tx = tid & 31, ty = tid >> 5;
#pragma unroll
    for (int i = 0; i < 4; i++) {
        int k = kt*32 + ty + i*8, n = nt*32 + tx;
        t[ty + i*8][tx] = W[(size_t)k*N + n];
    }
    __syncthreads();
#pragma unroll
    for (int i = 0; i < 4; i++) {
        int n = nt*32 + ty + i*8, k = kt*32 + tx;
        split_bf(t[tx][ty + i*8], oh[(size_t)n*K + k], ol[(size_t)n*K + k]);
    }
}
__global__ void mark_k(const int* __restrict__ ids)
{
    int t = blockIdx.x * blockDim.x + threadIdx.x;
    if (t < NTOK) g_present[ids[t]] = 1;
}
__global__ void scan1_k()
{
    __shared__ int s[1024];
    int t = threadIdx.x, g = blockIdx.x * 1024 + t;
    int p = g_present[g];
    s[t] = p; __syncthreads();
    for (int off = 1; off < 1024; off <<= 1) {
        int v = (t >= off) ? s[t - off] : 0;
        __syncthreads();
        s[t] += v;
        __syncthreads();
    }
    g_cidx[g] = s[t] - p;
    if (t == 1023) g_bsum[blockIdx.x] = s[t];
}
__global__ void scan3_k()
{
    __shared__ int off_s;
    int t = threadIdx.x, g = blockIdx.x * 1024 + t;
    if (t == 0) {
        int run = 0;
        for (int i = 0; i < (int)blockIdx.x; i++) run += g_bsum[i];
        off_s = run;
        if (blockIdx.x == 63) g_ucnt[0] = run + g_bsum[63];
    }
    __syncthreads();
    int c = g_cidx[g] + off_s;
    g_cidx[g] = c;
    if (g_present[g]) g_ulist[c] = g;
}
__global__ void tokc_k(const int* __restrict__ ids)
{
    int t = blockIdx.x * blockDim.x + threadIdx.x;
    if (t < NTOK) g_tokc[t] = g_cidx[ids[t]];
}

// ---------------------------------------------------------------------------
// Shared engine constants
// ---------------------------------------------------------------------------
#define A_STRB 40
#define A_PL   (128*A_STRB)                 // 5120 bf16
#define B_PL   (256*A_STRB)                 // 10240 bf16
#define BUF_E  (2*A_PL + 2*B_PL)            // 30720 bf16
#define BUF_B  (BUF_E*2)                    // 61440 bytes
#define GEMM_SMEM (2*BUF_B)                 // 122880 bytes

// 128-wide engine: 256 threads, 2 CTAs/SM
#define B128_PL (128*A_STRB)                // 5120 bf16
#define BUF128_E (2*A_PL + 2*B128_PL)       // 20480 bf16
#define BUF128_B (BUF128_E*2)               // 40960 bytes
#define G128_SMEM (2*BUF128_B)              // 81920 bytes

// ---------------------------------------------------------------------------
// gemm_bf: proven 512-thread, N=256-wide engine with fused-LN epilogue.
// Used ONLY for GEMM2 (LN needs full 256-wide rows in one CTA).
// Numerics: hh,lh,hl per k16, k ascending (deterministic per row).
// ---------------------------------------------------------------------------
__global__ void __launch_bounds__(512, 1) gemm_bf(
    const bf16* __restrict__ AhG, const bf16* __restrict__ AlG,
    const bf16* __restrict__ Bh0, const bf16* __restrict__ Bl0,
    const float* __restrict__ bias0,
    int Kdim,
    const int* __restrict__ ucntp,
    bf16* __restrict__ Ch, bf16* __restrict__ Cl,
    const float* __restrict__ lng, const float* __restrict__ lnb)
{
    extern __shared__ bf16 smbf[];
    const int bm = blockIdx.x * 128;
    if (bm >= ucntp[0]) return;
    const int Ndim = 256;
    const bf16 *BhG = Bh0, *BlG = Bl0;
    const float* bias_ = bias0;

    const int tid = threadIdx.x;
    const int wid = tid >> 5, lane = tid & 31;
    const int wm = (wid >> 2) * 32, wn = (wid & 3) * 64;
    const int grp = lane >> 2, qd = lane & 3;

    const int fa_row = tid >> 2, fa_q = tid & 3;
    const int fb_row = tid >> 1, fb_h = tid & 1;

    const bf16* AhR = AhG + (size_t)(bm + fa_row) * Kdim + fa_q * 8;
    const bf16* AlR = AlG + (size_t)(bm + fa_row) * Kdim + fa_q * 8;
    const bf16* BhR = BhG + (size_t)fb_row * Kdim;
    const bf16* BlR = BlG + (size_t)fb_row * Kdim;

    float acc[2][8][4];
#pragma unroll
    for (int mi = 0; mi < 2; mi++)
#pragma unroll
        for (int ni = 0; ni < 8; ni++)
#pragma unroll
            for (int j = 0; j < 4; j++) acc[mi][ni][j] = 0.f;

    const int ktiles = Kdim >> 5;
    const uint32_t smBase = s2u(smbf);
    const uint32_t aFrag = (uint32_t)((wm + (lane & 15)) * (A_STRB*2)) + ((lane >> 4) * 16);
    const uint32_t bFrag = (uint32_t)(2*A_PL*2) +
        (uint32_t)((wn + (lane & 7) + ((lane >> 4) & 1) * 8) * (A_STRB*2)) +
        (((lane >> 3) & 1) * 16);

    auto stage = [&](int bufo, int kt) {
        uint32_t dh = smBase + bufo + 2*A_PL*2 + (fb_row*A_STRB + fb_h*16) * 2;
        uint32_t dl = dh + B_PL*2;
        const bf16* sh = BhR + kt*32 + fb_h*16;
        const bf16* sl = BlR + kt*32 + fb_h*16;
        cpasync16(dh,      sh);
        cpasync16(dh + 16, sh + 8);
        cpasync16(dl,      sl);
        cpasync16(dl + 16, sl + 8);
        uint32_t da = smBase + bufo + (fa_row*A_STRB + fa_q*8) * 2;
        cpasync16(da,            AhR + kt*32);
        cpasync16(da + A_PL*2,   AlR + kt*32);
        CP_COMMIT();
    };

    stage(0, 0);
    CP_WAIT0();
    __syncthreads();

    for (int kt = 0; kt < ktiles; kt++) {
        const int curo = (kt & 1) * BUF_B;
        const int nxto = curo ^ BUF_B;
        const bool more = (kt + 1 < ktiles);
        if (more) stage(nxto, kt + 1);

#pragma unroll
        for (int k16 = 0; k16 < 2; k16++) {
            uint32_t aH[2][4], aL[2][4];
#pragma unroll
            for (int mi = 0; mi < 2; mi++) {
                uint32_t addr = smBase + curo + aFrag + mi*16*(A_STRB*2) + k16*32;
                ldsm_x4(aH[mi], addr);
                ldsm_x4(aL[mi], addr + A_PL*2);
            }
#pragma unroll
            for (int nig = 0; nig < 4; nig++) {
                uint32_t bH[4], bL[4];
                uint32_t addr = smBase + curo + bFrag + nig*16*(A_STRB*2) + k16*32;
                ldsm_x4(bH, addr);
                ldsm_x4(bL, addr + B_PL*2);
#pragma unroll
                for (int s = 0; s < 2; s++)
#pragma unroll
                    for (int mi = 0; mi < 2; mi++)
                        mma_bf16(acc[mi][nig*2+s], aH[mi], bH[2*s], bH[2*s+1]);
#pragma unroll
                for (int s = 0; s < 2; s++)
#pragma unroll
                    for (int mi = 0; mi < 2; mi++)
                        mma_bf16(acc[mi][nig*2+s], aL[mi], bH[2*s], bH[2*s+1]);
#pragma unroll
                for (int s = 0; s < 2; s++)
#pragma unroll
                    for (int mi = 0; mi < 2; mi++)
                        mma_bf16(acc[mi][nig*2+s], aH[mi], bL[2*s], bL[2*s+1]);
            }
        }

        if (more) CP_WAIT0();
        __syncthreads();
    }

    // fused LayerNorm epilogue (full 256-wide rows in-CTA)
    float* red = (float*)smbf;          // [128][17] padded
    float* mus = red + 128*17;
    float* sis = mus + 128;
    const int slot = (wid & 3)*4 + qd;

#pragma unroll
    for (int mi = 0; mi < 2; mi++) {
        const int lr = wm + mi*16 + grp;
        float s0 = 0.f, s1 = 0.f;
#pragma unroll
        for (int ni = 0; ni < 8; ni++) {
            const int n = wn + ni*8 + qd*2;
            float b0 = bias_[n], b1 = bias_[n+1];
            acc[mi][ni][0] += b0; acc[mi][ni][1] += b1;
            acc[mi][ni][2] += b0; acc[mi][ni][3] += b1;
            s0 += acc[mi][ni][0] + acc[mi][ni][1];
            s1 += acc[mi][ni][2] + acc[mi][ni][3];
        }
        red[lr*17 + slot]     = s0;
        red[(lr+8)*17 + slot] = s1;
    }
    __syncthreads();
    if (tid < 128) {
        float m = 0.f;
#pragma unroll
        for (int s = 0; s < 16; s++) m += red[tid*17 + s];
        mus[tid] = m * (1.f/DM);
    }
    __syncthreads();
#pragma unroll
    for (int mi = 0; mi < 2; mi++) {
        const int lr = wm + mi*16 + grp;
        float mu0 = mus[lr], mu1 = mus[lr+8];
        float s0 = 0.f, s1 = 0.f;
#pragma unroll
        for (int ni = 0; ni < 8; ni++) {
            float c0 = acc[mi][ni][0]-mu0, c1 = acc[mi][ni][1]-mu0;
            float c2 = acc[mi][ni][2]-mu1, c3 = acc[mi][ni][3]-mu1;
            s0 += c0*c0 + c1*c1;
            s1 += c2*c2 + c3*c3;
        }
        red[lr*17 + slot]     = s0;
        red[(lr+8)*17 + slot] = s1;
    }
    __syncthreads();
    if (tid < 128) {
        float v = 0.f;
#pragma unroll
        for (int s = 0; s < 16; s++) v += red[tid*17 + s];
        sis[tid] = rsqrtf(v * (1.f/DM) + 1e-5f);
    }
    __syncthreads();
#pragma unroll
    for (int mi = 0; mi < 2; mi++) {
        const int lr = wm + mi*16 + grp;
        const int r0 = bm + lr;
        float mu0 = mus[lr], is0 = sis[lr];
        float mu1 = mus[lr+8], is1 = sis[lr+8];
#pragma unroll
        for (int ni = 0; ni < 8; ni++) {
            const int n = wn + ni*8 + qd*2;
            float g0 = lng[n], g1 = lng[n+1], e0 = lnb[n], e1 = lnb[n+1];
            float v0 = g0*(acc[mi][ni][0]-mu0)*is0 + e0;
            float v1 = g1*(acc[mi][ni][1]-mu0)*is0 + e1;
            float v2 = g0*(acc[mi][ni][2]-mu1)*is1 + e0;
            float v3 = g1*(acc[mi][ni][3]-mu1)*is1 + e1;
            bf16 h0,l0,h1,l1,h2,l2,h3,l3;
            split_bf(v0,h0,l0); split_bf(v1,h1,l1);
            split_bf(v2,h2,l2); split_bf(v3,h3,l3);
            *(uint32_t*)&Ch[(size_t)r0 * Ndim + n]     = pack2(h0, h1);
            *(uint32_t*)&Ch[(size_t)(r0+8) * Ndim + n] = pack2(h2, h3);
            *(uint32_t*)&Cl[(size_t)r0 * Ndim + n]     = pack2(l0, l1);
            *(uint32_t*)&Cl[(size_t)(r0+8) * Ndim + n] = pack2(l2, l3);
        }
    }
}

// ---------------------------------------------------------------------------
// gemm_b128: 256-thread, N=128-per-CTA engine, 2 CTAs/SM (regfile allows
// 256thr x 128regs x 2). 8 warps (4m x 2n, warp tile 32x64). 2-stage buffer.
// blockIdx.x low 2 bits = column/output selector (A-sharing CTAs adjacent):
//   dual=0: bn = yv*128 within one output of width NdimC
//   dual=1: output sel = yv>>1, bn = (yv&1)*128, each output 256 wide
// Per-element accumulation order identical to gemm_bf (hh,lh,hl per k16,
// k ascending) => results bitwise identical to the 512-thread engine.
// ---------------------------------------------------------------------------
__global__ void __launch_bounds__(256, 2) gemm_b128(
    const float* __restrict__ Araw,
    const bf16* __restrict__ AhG, const bf16* __restrict__ AlG,
    const bf16* __restrict__ Bh0, const bf16* __restrict__ Bl0,
    float* __restrict__ C0, const float* __restrict__ bias0,
    const bf16* __restrict__ Bh1, const bf16* __restrict__ Bl1,
    float* __restrict__ C1, const float* __restrict__ bias1,
    int Kdim, int NdimC,
    const int* __restrict__ gather,
    int act,
    const int* __restrict__ ucntp,
    int dual,
    bf16* __restrict__ Ch, bf16* __restrict__ Cl)
{
    extern __shared__ bf16 smbf[];
    const int bxm = blockIdx.x >> 2, yv = blockIdx.x & 3;
    const int bm = bxm * 128;
    if (bm >= ucntp[0]) return;

    const bf16 *BhG, *BlG;
    const float* bias_;
    float* Cp;
    int bn;
    if (dual) {
        if (yv >> 1) { BhG = Bh1; BlG = Bl1; Cp = C1; bias_ = bias1; }
        else         { BhG = Bh0; BlG = Bl0; Cp = C0; bias_ = bias0; }
        bn = (yv & 1) * 128;
    } else {
        BhG = Bh0; BlG = Bl0; Cp = C0; bias_ = bias0;
        bn = yv * 128;
    }

    const int tid = threadIdx.x;
    const int wid = tid >> 5, lane = tid & 31;
    const int wm = (wid >> 1) * 32, wn = (wid & 1) * 64;
    const int grp = lane >> 2, qd = lane & 3;

    // fill mapping: 2 threads per row, each 16 elems (32 B) per plane
    const int f_row = tid >> 1, f_h = tid & 1;

    int ar = bm + f_row;
    if (gather) ar = gather[ar];
    const bool gatherA = (Araw != nullptr);
    const float* ApR = gatherA ? (Araw + (size_t)ar * Kdim + f_h * 16) : nullptr;
    const bf16* AhR = gatherA ? nullptr : (AhG + (size_t)(bm + f_row) * Kdim + f_h * 16);
    const bf16* AlR = gatherA ? nullptr : (AlG + (size_t)(bm + f_row) * Kdim + f_h * 16);
    const bf16* BhR = BhG + (size_t)(bn + f_row) * Kdim + f_h * 16;
    const bf16* BlR = BlG + (size_t)(bn + f_row) * Kdim + f_h * 16;

    float acc[2][8][4];
#pragma unroll
    for (int mi = 0; mi < 2; mi++)
#pragma unroll
        for (int ni = 0; ni < 8; ni++)
#pragma unroll
            for (int j = 0; j < 4; j++) acc[mi][ni][j] = 0.f;

    const int ktiles = Kdim >> 5;
    const uint32_t smBase = s2u(smbf);
    const uint32_t aFrag = (uint32_t)((wm + (lane & 15)) * (A_STRB*2)) + ((lane >> 4) * 16);
    const uint32_t bFrag = (uint32_t)(2*A_PL*2) +
        (uint32_t)((wn + (lane & 7) + ((lane >> 4) & 1) * 8) * (A_STRB*2)) +
        (((lane >> 3) & 1) * 16);

    auto stage = [&](int bufo, int kt) {
        // B planes (128 rows)
        uint32_t db = smBase + bufo + 2*A_PL*2 + (f_row*A_STRB + f_h*16) * 2;
        cpasync16(db,               BhR + kt*32);
        cpasync16(db + 16,          BhR + kt*32 + 8);
        cpasync16(db + B128_PL*2,      BlR + kt*32);
        cpasync16(db + B128_PL*2 + 16, BlR + kt*32 + 8);
        // A planes
        if (gatherA) {
            float4 v0 = *(const float4*)(ApR + kt*32);
            float4 v1 = *(const float4*)(ApR + kt*32 + 4);
            float4 v2 = *(const float4*)(ApR + kt*32 + 8);
            float4 v3 = *(const float4*)(ApR + kt*32 + 12);
            bf16 h[16], l[16];
            split_bf(v0.x,h[0],l[0]);  split_bf(v0.y,h[1],l[1]);
            split_bf(v0.z,h[2],l[2]);  split_bf(v0.w,h[3],l[3]);
            split_bf(v1.x,h[4],l[4]);  split_bf(v1.y,h[5],l[5]);
            split_bf(v1.z,h[6],l[6]);  split_bf(v1.w,h[7],l[7]);
            split_bf(v2.x,h[8],l[8]);  split_bf(v2.y,h[9],l[9]);
            split_bf(v2.z,h[10],l[10]); split_bf(v2.w,h[11],l[11]);
            split_bf(v3.x,h[12],l[12]); split_bf(v3.y,h[13],l[13]);
            split_bf(v3.z,h[14],l[14]); split_bf(v3.w,h[15],l[15]);
            uint32_t off = bufo + (f_row*A_STRB + f_h*16) * 2;
            uint4 ph0 = make_uint4(pack2(h[0],h[1]),  pack2(h[2],h[3]),
                                   pack2(h[4],h[5]),  pack2(h[6],h[7]));
            uint4 ph1 = make_uint4(pack2(h[8],h[9]),  pack2(h[10],h[11]),
                                   pack2(h[12],h[13]),pack2(h[14],h[15]));
            uint4 pl0 = make_uint4(pack2(l[0],l[1]),  pack2(l[2],l[3]),
                                   pack2(l[4],l[5]),  pack2(l[6],l[7]));
            uint4 pl1 = make_uint4(pack2(l[8],l[9]),  pack2(l[10],l[11]),
                                   pack2(l[12],l[13]),pack2(l[14],l[15]));
            *(uint4*)((char*)smbf + off)                = ph0;
            *(uint4*)((char*)smbf + off + 16)           = ph1;
            *(uint4*)((char*)smbf + off + A_PL*2)       = pl0;
            *(uint4*)((char*)smbf + off + A_PL*2 + 16)  = pl1;
        } else {
            uint32_t da = smBase + bufo + (f_row*A_STRB + f_h*16) * 2;
            cpasync16(da,              AhR + kt*32);
            cpasync16(da + 16,         AhR + kt*32 + 8);
            cpasync16(da + A_PL*2,     AlR + kt*32);
            cpasync16(da + A_PL*2 + 16,AlR + kt*32 + 8);
        }
        CP_COMMIT();
    };

    stage(0, 0);
    CP_WAIT0();
    __syncthreads();

    for (int kt = 0; kt < ktiles; kt++) {
        const int curo = (kt & 1) * BUF128_B;
        const int nxto = curo ^ BUF128_B;
        const bool more = (kt + 1 < ktiles);
        if (more) stage(nxto, kt + 1);

#pragma unroll
        for (int k16 = 0; k16 < 2; k16++) {
            uint32_t aH[2][4], aL[2][4];
#pragma unroll
            for (int mi = 0; mi < 2; mi++) {
                uint32_t addr = smBase + curo + aFrag + mi*16*(A_STRB*2) + k16*32;
                ldsm_x4(aH[mi], addr);
                ldsm_x4(aL[mi], addr + A_PL*2);
            }
#pragma unroll
            for (int nig = 0; nig < 4; nig++) {
                uint32_t bH[4], bL[4];
                uint32_t addr = smBase + curo + bFrag + nig*16*(A_STRB*2) + k16*32;
                ldsm_x4(bH, addr);
                ldsm_x4(bL, addr + B128_PL*2);
#pragma unroll
                for (int s = 0; s < 2; s++)
#pragma unroll
                    for (int mi = 0; mi < 2; mi++)
                        mma_bf16(acc[mi][nig*2+s], aH[mi], bH[2*s], bH[2*s+1]);
#pragma unroll
                for (int s = 0; s < 2; s++)
#pragma unroll
                    for (int mi = 0; mi < 2; mi++)
                        mma_bf16(acc[mi][nig*2+s], aL[mi], bH[2*s], bH[2*s+1]);
#pragma unroll
                for (int s = 0; s < 2; s++)
#pragma unroll
                    for (int mi = 0; mi < 2; mi++)
                        mma_bf16(acc[mi][nig*2+s], aH[mi], bL[2*s], bL[2*s+1]);
            }
        }

        if (more) CP_WAIT0();
        __syncthreads();
    }

    // epilogue
#pragma unroll
    for (int mi = 0; mi < 2; mi++) {
        const int r0 = bm + wm + mi*16 + grp;
#pragma unroll
        for (int ni = 0; ni < 8; ni++) {
            const int n = bn + wn + ni*8 + qd*2;
            float b0 = bias_ ? bias_[n]   : 0.f;
            float b1 = bias_ ? bias_[n+1] : 0.f;
            float v0 = acc[mi][ni][0] + b0, v1 = acc[mi][ni][1] + b1;
            float v2 = acc[mi][ni][2] + b0, v3 = acc[mi][ni][3] + b1;
            if (act == 1) {
                v0 = fmaxf(v0, 0.f); v1 = fmaxf(v1, 0.f);
                v2 = fmaxf(v2, 0.f); v3 = fmaxf(v3, 0.f);
            }
            if (Cp) {
                *(float2*)&Cp[(size_t)r0 * NdimC + n]     = make_float2(v0, v1);
                *(float2*)&Cp[(size_t)(r0+8) * NdimC + n] = make_float2(v2, v3);
            }
            if (Ch) {
                bf16 h0,l0,h1,l1,h2,l2,h3,l3;
                split_bf(v0,h0,l0); split_bf(v1,h1,l1);
                split_bf(v2,h2,l2); split_bf(v3,h3,l3);
                *(uint32_t*)&Ch[(size_t)r0 * NdimC + n]     = pack2(h0, h1);
                *(uint32_t*)&Ch[(size_t)(r0+8) * NdimC + n] = pack2(h2, h3);
                *(uint32_t*)&Cl[(size_t)r0 * NdimC + n]     = pack2(l0, l1);
                *(uint32_t*)&Cl[(size_t)(r0+8) * NdimC + n] = pack2(l2, l3);
            }
        }
    }
}

// ---------------------------------------------------------------------------
// Per-(b,l) precompute
// ---------------------------------------------------------------------------
__global__ void prep_k(const float* __restrict__ v, const float* __restrict__ tv,
                       const float* __restrict__ am_w1, const float* __restrict__ am_b1,
                       const float* __restrict__ wq)
{
    __shared__ float tvs[DM];
    __shared__ float qs[DM];
    int bl = blockIdx.x, d = threadIdx.x;
    float t0 = tv[(size_t)bl*DM + d];
    tvs[d] = t0;
    qs[d]  = t0 + v[(size_t)bl*DM + d];
    __syncthreads();
    float t = am_b1[d], q = 0.f;
    for (int k = 0; k < DM; k++) {
        t = fmaf(tvs[k], am_w1[k*DM + d], t);
        q = fmaf(qs[k],  wq  [k*DM + d], q);
    }
    g_T [(size_t)bl*DM + d] = t;
    g_QW[(size_t)bl*DM + d] = q;
}

// ---------------------------------------------------------------------------
// Fused per-visit score + stable sort (one block per (b,l) visit).
// ---------------------------------------------------------------------------
__global__ void scorsel_k(const float* __restrict__ am_w2,
                          const int* __restrict__ masks)
{
    int bl = blockIdx.x;
    int tid = threadIdx.x, wid = tid >> 5, lane = tid & 31;
    __shared__ float key[64];

    const float4* tt4 = (const float4*)(g_T + (size_t)bl * DM);
    const float4* w4  = (const float4*)am_w2;
    float4 t0 = tt4[lane*2], t1 = tt4[lane*2+1];
    float4 w0 = w4[lane*2],  w1 = w4[lane*2+1];

#pragma unroll
    for (int i = 0; i < 8; i++) {
        int j = wid*8 + i;
        int tok = bl*64 + j;
        int c = g_tokc[tok];
        const float4* s24 = (const float4*)(g_S2 + (size_t)c * DM);
        float4 a0 = s24[lane*2], a1 = s24[lane*2+1];
        float s = 0.f;
        s = fmaf(tanhf(a0.x + t0.x), w0.x, s);
        s = fmaf(tanhf(a0.y + t0.y), w0.y, s);
        s = fmaf(tanhf(a0.z + t0.z), w0.z, s);
        s = fmaf(tanhf(a0.w + t0.w), w0.w, s);
        s = fmaf(tanhf(a1.x + t1.x), w1.x, s);
        s = fmaf(tanhf(a1.y + t1.y), w1.y, s);
        s = fmaf(tanhf(a1.z + t1.z), w1.z, s);
        s = fmaf(tanhf(a1.w + t1.w), w1.w, s);
        for (int o = 16; o > 0; o >>= 1) s += __shfl_down_sync(0xffffffffu, s, o);
        if (lane == 0) key[j] = masks[tok] ? s : neg_inf();
    }
    __syncthreads();

    if (tid < 64) {
        int j = tid;
        float k_ = key[j];
        int rank = 0;
        for (int m = 0; m < 64; m++) {
            float o = key[m];
            rank += (o > k_) || (o == k_ && m < j);
        }
        g_selslot[bl*64 + rank] = (bl % LSEQ) * NBLK + j;
    }
}

// ---------------------------------------------------------------------------
// Sequential memory recurrence (batch-resident smem; half-warp candidates)
// ---------------------------------------------------------------------------
__global__ void recur_k(const int* __restrict__ ids, const int* __restrict__ masks,
                        const int* __restrict__ lens)
{
    extern __shared__ float dsm[];
    float* qall  = dsm;
    int*   sel_s = (int*)(qall + LSEQ*DM);
    int*   msk_s = sel_s + SLOTS;
    int*   tok_s = msk_s + SLOTS;

    int b = blockIdx.x, tid = threadIdx.x;
    __shared__ int cslot[64], cmask[64];
    __shared__ int nslot[64], nmask[64];
    __shared__ int dslot[128], dmask[128], dcid[128];
    __shared__ float ev[128];
    __shared__ __align__(16) float mk[128];

    {
        const float4* src = (const float4*)(g_QW + (size_t)b * LSEQ * DM);
        float4* dst = (float4*)qall;
        for (int i = tid; i < LSEQ*DM/4; i += 256) dst[i] = src[i];
        const int4* ss = (const int4*)(g_selslot + b * SLOTS);
        const int4* ms = (const int4*)(masks + b * SLOTS);
        const int4* ts = (const int4*)(g_tokc + b * SLOTS);
        for (int i = tid; i < SLOTS/4; i += 256) {
            ((int4*)sel_s)[i] = ss[i];
            ((int4*)msk_s)[i] = ms[i];
            ((int4*)tok_s)[i] = ts[i];
        }
    }
    int lb = lens[b];
    __syncthreads();

    if (tid < 64) {
        int slot = sel_s[0*64 + tid];
        cslot[tid] = slot;
        cmask[tid] = msk_s[slot];
    }
    __syncthreads();

    const int hw = tid >> 4, hl = tid & 15;

    for (int t = 1; t < LSEQ; t++) {
        if (tid < 128) {
            int slot = (tid < 64) ? cslot[tid] : sel_s[t*64 + (tid - 64)];
            dslot[tid] = slot;
            dmask[tid] = (tid < 64) ? cmask[tid] : msk_s[slot];
            dcid [tid] = tok_s[slot];
        }
        __syncthreads();

        const float4* q4 = (const float4*)(qall + (size_t)t * DM);
        float4 qv0 = q4[hl], qv1 = q4[hl+16], qv2 = q4[hl+32], qv3 = q4[hl+48];
        const float4* kv = (const float4*)(g_KV + (size_t)dcid[hw] * DM);
        float4 k0 = kv[hl], k1 = kv[hl+16], k2 = kv[hl+32], k3 = kv[hl+48];
        for (int c = hw; c < 128; c += 16) {
            const bool hasnext = (c + 16 < 128);
            float4 n0, n1, n2, n3;
            if (hasnext) {
                const float4* kn = (const float4*)(g_KV + (size_t)dcid[c + 16] * DM);
                n0 = kn[hl]; n1 = kn[hl+16]; n2 = kn[hl+32]; n3 = kn[hl+48];
            }
            float s = k0.x*qv0.x + k0.y*qv0.y + k0.z*qv0.z + k0.w*qv0.w
                    + k1.x*qv1.x + k1.y*qv1.y + k1.z*qv1.z + k1.w*qv1.w
                    + k2.x*qv2.x + k2.y*qv2.y + k2.z*qv2.z + k2.w*qv2.w
                    + k3.x*qv3.x + k3.y*qv3.y + k3.z*qv3.z + k3.w*qv3.w;
            for (int o = 8; o > 0; o >>= 1) s += __shfl_down_sync(0xffffffffu, s, o, 16);
            if (hl == 0) ev[c] = s;
            if (hasnext) { k0 = n0; k1 = n1; k2 = n2; k3 = n3; }
        }
        __syncthreads();

        if (tid < 128) mk[tid] = dmask[tid] ? ev[tid] : neg_inf();
        __syncthreads();

        if (tid < 128) {
            float k_ = mk[tid];
            int rank = 0;
            const float4* m4 = (const float4*)mk;
#pragma unroll 8
            for (int i = 0; i < 32; i++) {
                float4 o4 = m4[i];
                int mb = i*4;
                rank += (o4.x > k_) || (o4.x == k_ && mb+0 < tid);
                rank += (o4.y > k_) || (o4.y == k_ && mb+1 < tid);
                rank += (o4.z > k_) || (o4.z == k_ && mb+2 < tid);
                rank += (o4.w > k_) || (o4.w == k_ && mb+3 < tid);
            }
            if (rank < 64) { nslot[rank] = dslot[tid]; nmask[rank] = dmask[tid]; }
        }
        __syncthreads();
        if (tid < 64) {
            cslot[tid] = nslot[tid];
            cmask[tid] = nmask[tid];
            if (t == lb - 1) g_fslot[b*64 + tid] = nslot[tid];
        }
        __syncthreads();
    }
}

// ---------------------------------------------------------------------------
// Pools (VT reconstructed as hi+lo; max-pool path, 1e-3 tolerance)
// ---------------------------------------------------------------------------
__global__ void final_k(const float* __restrict__ tv, const int* __restrict__ ids,
                        const int* __restrict__ lens)
{
    int b = blockIdx.x, d = threadIdx.x;
    int lb = lens[b];
    float mx = neg_inf();
    for (int l = 0; l < lb; l++) mx = fmaxf(mx, tv[((size_t)b*LSEQ + l)*DM + d]);
    g_vfin[b*DM + d] = mx;
    float mv = neg_inf();
    for (int m = 0; m < 64; m++) {
        int c = g_tokc[b*SLOTS + g_fslot[b*64 + m]];
        float vt = __bfloat162float(g_VTh[(size_t)c*DM + d])
                 + __bfloat162float(g_VTl[(size_t)c*DM + d]);
        mv = fmaxf(mv, vt);
    }
    g_mfin[b*DM + d] = mv;
    if (d < 64) g_fid[b*64 + d] = ids[b*SLOTS + g_fslot[b*64 + d]];
}

// ---------------------------------------------------------------------------
// Output head + flatten
// ---------------------------------------------------------------------------
__global__ void out_k(const float* __restrict__ ow, const float* __restrict__ ob,
                      float* __restrict__ out, int out_size)
{
    int tid = threadIdx.x;
    if (tid < 32) {
        int b = tid >> 1, o = tid & 1;
        float v = ob[o];
        for (int d = 0; d < DM; d++) v = fmaf(g_vfin[b*DM + d], ow[d*2 + o], v);
        for (int d = 0; d < DM; d++) v = fmaf(g_mfin[b*DM + d], ow[(DM + d)*2 + o], v);
        if (tid < out_size) out[tid] = v;
    }
    for (int i = tid; i < BSZ*64; i += blockDim.x)
        if (32 + i < out_size) out[32 + i] = (float)g_fid[i];
    for (int i = 32 + BSZ*64 + tid; i < out_size; i += blockDim.x)
        out[i] = 0.f;
}

// ---------------------------------------------------------------------------
// Launch
// ---------------------------------------------------------------------------
extern "C" void kernel_launch(void* const* d_in, const int* in_sizes, int n_in,
                              void* d_out, int out_size)
{
    const float* v_all  = (const float*)d_in[0];
    const float* tv_all = (const float*)d_in[1];
    const float* emb    = (const float*)d_in[2];
    const float* w1     = (const float*)d_in[3];
    const float* b1     = (const float*)d_in[4];
    const float* w2     = (const float*)d_in[5];
    const float* b2     = (const float*)d_in[6];
    const float* gam    = (const float*)d_in[7];
    const float* bet    = (const float*)d_in[8];
    const float* wq     = (const float*)d_in[9];
    const float* wk     = (const float*)d_in[10];
    const float* amw1   = (const float*)d_in[11];
    const float* amb1   = (const float*)d_in[12];
    const float* amw2   = (const float*)d_in[13];
    const float* ow     = (const float*)d_in[14];
    const float* ob     = (const float*)d_in[15];
    const int*   itxt   = (const int*)d_in[16];
    const int*   mtxt   = (const int*)d_in[17];
    const int*   lens   = (const int*)d_in[18];
    float* out = (float*)d_out;

    bf16 *pHh, *pHl, *pVTh, *pVTl, *pBh, *pBl;
    float *pKV, *pS2;
    int *pU, *pUL;
    cudaGetSymbolAddress((void**)&pHh,  g_Hh);
    cudaGetSymbolAddress((void**)&pHl,  g_Hl);
    cudaGetSymbolAddress((void**)&pVTh, g_VTh);
    cudaGetSymbolAddress((void**)&pVTl, g_VTl);
    cudaGetSymbolAddress((void**)&pKV,  g_KV);
    cudaGetSymbolAddress((void**)&pS2,  g_S2);
    cudaGetSymbolAddress((void**)&pBh,  g_Bh);
    cudaGetSymbolAddress((void**)&pBl,  g_Bl);
    cudaGetSymbolAddress((void**)&pU,   g_ucnt);
    cudaGetSymbolAddress((void**)&pUL,  g_ulist);

    cudaFuncSetAttribute(gemm_bf,   cudaFuncAttributeMaxDynamicSharedMemorySize, GEMM_SMEM);
    cudaFuncSetAttribute(gemm_b128, cudaFuncAttributeMaxDynamicSharedMemorySize, G128_SMEM);
    const int recur_smem = (LSEQ*DM)*4 + 3*SLOTS*4;   // 89600 B
    cudaFuncSetAttribute(recur_k, cudaFuncAttributeMaxDynamicSharedMemorySize, recur_smem);

    // dedup + weight split
    prep0_k<<<640, 256>>>(w1, w2, wk, amw1 + DM*DM);
    mark_k<<<NTOK/256, 256>>>(itxt);
    scan1_k<<<64, 1024>>>();
    scan3_k<<<64, 1024>>>();

    // GEMM1: relu(emb[gather] @ w1 + b1) -> bf16 planes (4-way col interleave)
    gemm_b128<<<(NVOC/128)*4, 256, G128_SMEM>>>(
        emb, nullptr, nullptr,
        pBh + OFF_W1, pBl + OFF_W1, nullptr, b1,
        nullptr, nullptr, nullptr, nullptr,
        KD, DH, pUL, 1, pU, 0, pHh, pHl);

    tokc_k<<<NTOK/256, 256>>>(itxt);
    prep_k<<<NBL, DM>>>(v_all, tv_all, amw1, amb1, wq);

    // GEMM2 + fused LayerNorm: VT = LN(Hplanes @ w2 + b2) -> g_VTh/g_VTl
    gemm_bf<<<NVOC/128, 512, GEMM_SMEM>>>(
        pHh, pHl,
        pBh + OFF_W2, pBl + OFF_W2, b2,
        DH, pU, pVTh, pVTl, gam, bet);

    // GEMM3+4 dual: KV = VT @ wk ; S2 = VT @ am_w1[D:] (4-way interleave)
    gemm_b128<<<(NVOC/128)*4, 256, G128_SMEM>>>(
        nullptr, pVTh, pVTl,
        pBh + OFF_WK, pBl + OFF_WK, pKV, nullptr,
        pBh + OFF_AM, pBl + OFF_AM, pS2, nullptr,
        DM, DM, nullptr, 0, pU, 1, nullptr, nullptr);

    // fused score+selection, recurrence, pooling, head
    scorsel_k<<<NBL, 256>>>(amw2, mtxt);
    recur_k<<<BSZ, 256, recur_smem>>>(itxt, mtxt, lens);
    final_k<<<BSZ, DM>>>(tv_all, itxt, lens);
    out_k<<<1, 256>>>(ow, ob, out, out_size);
}